// round 1
// baseline (speedup 1.0000x reference)
#include <cuda_runtime.h>
#include <math.h>

#define CDIM 768
#define EXP 8
#define HDIM 3072
#define MAXN 8192

// ---- scratch (device globals; no cudaMalloc allowed) ----
__device__ int   d_fill[EXP];
__device__ int   d_off[EXP];
__device__ int   d_tok[EXP * MAXN];
__device__ float d_wgt[EXP * MAXN];
__device__ float d_hbuf[(size_t)2 * MAXN * HDIM];   // 2N x H fp32 (~201 MB)

// ---------------------------------------------------------------------------
// zero output + reset per-expert fill counters
// ---------------------------------------------------------------------------
__global__ void zero_kernel(float* __restrict__ out, int total) {
    int idx = blockIdx.x * blockDim.x + threadIdx.x;
    if (idx < total) out[idx] = 0.0f;
    if (blockIdx.x == 0 && threadIdx.x < EXP) d_fill[threadIdx.x] = 0;
}

// ---------------------------------------------------------------------------
// router: 1 warp per token. logits = x_n @ Wr -> softmax -> top2 -> weights
// ---------------------------------------------------------------------------
__global__ void router_kernel(const float* __restrict__ x,
                              const float* __restrict__ Wr, int N) {
    int gw   = (blockIdx.x * blockDim.x + threadIdx.x) >> 5;
    int lane = threadIdx.x & 31;
    if (gw >= N) return;
    const float* xr = x + (size_t)gw * CDIM;

    float acc[EXP];
#pragma unroll
    for (int e = 0; e < EXP; e++) acc[e] = 0.0f;

    for (int k = lane; k < CDIM; k += 32) {
        float xv = xr[k];
        const float4* w4 = reinterpret_cast<const float4*>(Wr + (size_t)k * EXP);
        float4 w0 = w4[0], w1 = w4[1];
        acc[0] += xv * w0.x; acc[1] += xv * w0.y;
        acc[2] += xv * w0.z; acc[3] += xv * w0.w;
        acc[4] += xv * w1.x; acc[5] += xv * w1.y;
        acc[6] += xv * w1.z; acc[7] += xv * w1.w;
    }
#pragma unroll
    for (int e = 0; e < EXP; e++) {
#pragma unroll
        for (int off = 16; off > 0; off >>= 1)
            acc[e] += __shfl_xor_sync(0xFFFFFFFFu, acc[e], off);
    }

    if (lane == 0) {
        float m = acc[0];
#pragma unroll
        for (int e = 1; e < EXP; e++) m = fmaxf(m, acc[e]);
        float p[EXP], s = 0.0f;
#pragma unroll
        for (int e = 0; e < EXP; e++) { p[e] = expf(acc[e] - m); s += p[e]; }
        float inv = 1.0f / s;
#pragma unroll
        for (int e = 0; e < EXP; e++) p[e] *= inv;

        int i1 = 0;
#pragma unroll
        for (int e = 1; e < EXP; e++) if (p[e] > p[i1]) i1 = e;
        int i2 = (i1 == 0) ? 1 : 0;
#pragma unroll
        for (int e = 0; e < EXP; e++)
            if (e != i1 && p[e] > p[i2]) i2 = e;

        float denom = p[i1] + p[i2] + 1e-9f;
        float w1 = p[i1] / denom;
        float w2 = p[i2] / denom;

        int s1 = atomicAdd(&d_fill[i1], 1);
        d_tok[i1 * MAXN + s1] = gw; d_wgt[i1 * MAXN + s1] = w1;
        int s2 = atomicAdd(&d_fill[i2], 1);
        d_tok[i2 * MAXN + s2] = gw; d_wgt[i2 * MAXN + s2] = w2;
    }
}

// ---------------------------------------------------------------------------
// exclusive prefix of per-expert counts
// ---------------------------------------------------------------------------
__global__ void offsets_kernel() {
    if (threadIdx.x == 0) {
        int o = 0;
        for (int e = 0; e < EXP; e++) { d_off[e] = o; o += d_fill[e]; }
    }
}

// ---------------------------------------------------------------------------
// GEMM1: h[row] = gelu( x[tok] @ W1[e] + b1[e] )   (gathered A rows)
// 64x64 tile, BK=16, 256 threads, 4x4 per thread, fp32
// ---------------------------------------------------------------------------
__global__ void __launch_bounds__(256)
gemm1_kernel(const float* __restrict__ x, const float* __restrict__ W1,
             const float* __restrict__ b1) {
    int e   = blockIdx.z;
    int cnt = d_fill[e];
    int m0  = blockIdx.x * 64;
    if (m0 >= cnt) return;
    int j0  = blockIdx.y * 64;

    __shared__ float As[64][17];
    __shared__ float Bs[16][64];

    int t  = threadIdx.x;
    int tx = t & 15, ty = t >> 4;
    const float* W1e = W1 + (size_t)e * CDIM * HDIM;

    int atok[4];
#pragma unroll
    for (int p = 0; p < 4; p++) {
        int gm = m0 + ty + p * 16;
        atok[p] = (gm < cnt) ? d_tok[e * MAXN + gm] : -1;
    }

    float acc[4][4];
#pragma unroll
    for (int r = 0; r < 4; r++)
#pragma unroll
        for (int c = 0; c < 4; c++) acc[r][c] = 0.0f;

    for (int k0 = 0; k0 < CDIM; k0 += 16) {
#pragma unroll
        for (int p = 0; p < 4; p++) {
            float v = 0.0f;
            if (atok[p] >= 0) v = x[(size_t)atok[p] * CDIM + k0 + tx];
            As[ty + p * 16][tx] = v;
        }
#pragma unroll
        for (int p = 0; p < 4; p++) {
            int kb = (t >> 6) + p * 4;
            int j  = t & 63;
            Bs[kb][j] = W1e[(size_t)(k0 + kb) * HDIM + j0 + j];
        }
        __syncthreads();
#pragma unroll
        for (int kk = 0; kk < 16; kk++) {
            float a0 = As[ty * 4 + 0][kk];
            float a1 = As[ty * 4 + 1][kk];
            float a2 = As[ty * 4 + 2][kk];
            float a3 = As[ty * 4 + 3][kk];
            float4 b = *reinterpret_cast<const float4*>(&Bs[kk][tx * 4]);
            acc[0][0] += a0 * b.x; acc[0][1] += a0 * b.y; acc[0][2] += a0 * b.z; acc[0][3] += a0 * b.w;
            acc[1][0] += a1 * b.x; acc[1][1] += a1 * b.y; acc[1][2] += a1 * b.z; acc[1][3] += a1 * b.w;
            acc[2][0] += a2 * b.x; acc[2][1] += a2 * b.y; acc[2][2] += a2 * b.z; acc[2][3] += a2 * b.w;
            acc[3][0] += a3 * b.x; acc[3][1] += a3 * b.y; acc[3][2] += a3 * b.z; acc[3][3] += a3 * b.w;
        }
        __syncthreads();
    }

    int off = d_off[e];
#pragma unroll
    for (int r = 0; r < 4; r++) {
        int gm = m0 + ty * 4 + r;
        if (gm < cnt) {
            size_t rowbase = (size_t)(off + gm) * HDIM + j0 + tx * 4;
#pragma unroll
            for (int c = 0; c < 4; c++) {
                float v = acc[r][c] + b1[e * HDIM + j0 + tx * 4 + c];
                v = 0.5f * v * (1.0f + erff(v * 0.70710678118654752f));
                d_hbuf[rowbase + c] = v;
            }
        }
    }
}

// ---------------------------------------------------------------------------
// GEMM2: y = h @ W2[e] + b2[e]; out[tok] += w * y  (atomic scatter)
// ---------------------------------------------------------------------------
__global__ void __launch_bounds__(256)
gemm2_kernel(const float* __restrict__ W2, const float* __restrict__ b2,
             float* __restrict__ out) {
    int e   = blockIdx.z;
    int cnt = d_fill[e];
    int m0  = blockIdx.x * 64;
    if (m0 >= cnt) return;
    int j0  = blockIdx.y * 64;
    int off = d_off[e];

    __shared__ float As[64][17];
    __shared__ float Bs[16][64];

    int t  = threadIdx.x;
    int tx = t & 15, ty = t >> 4;
    const float* W2e = W2 + (size_t)e * HDIM * CDIM;

    int avalid[4];
#pragma unroll
    for (int p = 0; p < 4; p++) avalid[p] = (m0 + ty + p * 16 < cnt);

    float acc[4][4];
#pragma unroll
    for (int r = 0; r < 4; r++)
#pragma unroll
        for (int c = 0; c < 4; c++) acc[r][c] = 0.0f;

    for (int k0 = 0; k0 < HDIM; k0 += 16) {
#pragma unroll
        for (int p = 0; p < 4; p++) {
            int gm = m0 + ty + p * 16;
            float v = 0.0f;
            if (avalid[p]) v = d_hbuf[(size_t)(off + gm) * HDIM + k0 + tx];
            As[ty + p * 16][tx] = v;
        }
#pragma unroll
        for (int p = 0; p < 4; p++) {
            int kb = (t >> 6) + p * 4;
            int j  = t & 63;
            Bs[kb][j] = W2e[(size_t)(k0 + kb) * CDIM + j0 + j];
        }
        __syncthreads();
#pragma unroll
        for (int kk = 0; kk < 16; kk++) {
            float a0 = As[ty * 4 + 0][kk];
            float a1 = As[ty * 4 + 1][kk];
            float a2 = As[ty * 4 + 2][kk];
            float a3 = As[ty * 4 + 3][kk];
            float4 b = *reinterpret_cast<const float4*>(&Bs[kk][tx * 4]);
            acc[0][0] += a0 * b.x; acc[0][1] += a0 * b.y; acc[0][2] += a0 * b.z; acc[0][3] += a0 * b.w;
            acc[1][0] += a1 * b.x; acc[1][1] += a1 * b.y; acc[1][2] += a1 * b.z; acc[1][3] += a1 * b.w;
            acc[2][0] += a2 * b.x; acc[2][1] += a2 * b.y; acc[2][2] += a2 * b.z; acc[2][3] += a2 * b.w;
            acc[3][0] += a3 * b.x; acc[3][1] += a3 * b.y; acc[3][2] += a3 * b.z; acc[3][3] += a3 * b.w;
        }
        __syncthreads();
    }

#pragma unroll
    for (int r = 0; r < 4; r++) {
        int gm = m0 + ty * 4 + r;
        if (gm < cnt) {
            int   tok = d_tok[e * MAXN + gm];
            float w   = d_wgt[e * MAXN + gm];
            size_t obase = (size_t)tok * CDIM + j0 + tx * 4;
#pragma unroll
            for (int c = 0; c < 4; c++) {
                float v = acc[r][c] + b2[e * CDIM + j0 + tx * 4 + c];
                atomicAdd(&out[obase + c], w * v);
            }
        }
    }
}

// ---------------------------------------------------------------------------
// utilization = counts / (sum + 1e-9)
// ---------------------------------------------------------------------------
__global__ void util_kernel(float* __restrict__ out, int NC) {
    int e = threadIdx.x;
    if (e < EXP) {
        float tot = 0.0f;
        for (int j = 0; j < EXP; j++) tot += (float)d_fill[j];
        out[NC + e] = (float)d_fill[e] / (tot + 1e-9f);
    }
}

// ---------------------------------------------------------------------------
extern "C" void kernel_launch(void* const* d_in, const int* in_sizes, int n_in,
                              void* d_out, int out_size) {
    const float* x  = (const float*)d_in[0];
    const float* Wr = (const float*)d_in[1];
    const float* W1 = (const float*)d_in[2];
    const float* b1 = (const float*)d_in[3];
    const float* W2 = (const float*)d_in[4];
    const float* b2 = (const float*)d_in[5];
    float* out = (float*)d_out;

    int N  = in_sizes[0] / CDIM;   // 8192
    int NC = N * CDIM;

    zero_kernel<<<(NC + 255) / 256, 256>>>(out, NC);
    router_kernel<<<(N + 7) / 8, 256>>>(x, Wr, N);
    offsets_kernel<<<1, 32>>>();

    dim3 g1((N + 63) / 64, HDIM / 64, EXP);
    gemm1_kernel<<<g1, 256>>>(x, W1, b1);

    dim3 g2((N + 63) / 64, CDIM / 64, EXP);
    gemm2_kernel<<<g2, 256>>>(W2, b2, out);

    util_kernel<<<1, 32>>>(out, NC);
}

// round 2
// speedup vs baseline: 2.0880x; 2.0880x over previous
#include <cuda_runtime.h>
#include <math.h>

#define CDIM 768
#define EXP 8
#define HDIM 3072
#define MAXN 8192

#define BM 128
#define BN 128
#define BK 16
#define AS_STRIDE 20     // (20*r + k) % 32 is a permutation over the frag-load pattern
#define BS_STRIDE 136    // (136*k + n) % 32 == (8k+n)%32 -> conflict-free

// ---- scratch (device globals; no cudaMalloc allowed) ----
__device__ int   d_fill[EXP];
__device__ int   d_off[EXP];
__device__ int   d_tok[EXP * MAXN];
__device__ float d_wgt[EXP * MAXN];
__device__ float d_hbuf[(size_t)2 * MAXN * HDIM];   // 2N x H fp32 (~201 MB)

__device__ __forceinline__ unsigned f2tf32(float f) {
    unsigned r;
    asm("cvt.rna.tf32.f32 %0, %1;" : "=r"(r) : "f"(f));
    return r;
}

__device__ __forceinline__ void mma_tf32(float* c, const unsigned* a, const unsigned* b) {
    asm volatile(
        "mma.sync.aligned.m16n8k8.row.col.f32.tf32.tf32.f32 "
        "{%0,%1,%2,%3}, {%4,%5,%6,%7}, {%8,%9}, {%0,%1,%2,%3};"
        : "+f"(c[0]), "+f"(c[1]), "+f"(c[2]), "+f"(c[3])
        : "r"(a[0]), "r"(a[1]), "r"(a[2]), "r"(a[3]), "r"(b[0]), "r"(b[1]));
}

// ---------------------------------------------------------------------------
// zero output + reset per-expert fill counters
// ---------------------------------------------------------------------------
__global__ void zero_kernel(float* __restrict__ out, int total) {
    int idx = blockIdx.x * blockDim.x + threadIdx.x;
    if (idx < total) out[idx] = 0.0f;
    if (blockIdx.x == 0 && threadIdx.x < EXP) d_fill[threadIdx.x] = 0;
}

// ---------------------------------------------------------------------------
// router: 1 warp per token
// ---------------------------------------------------------------------------
__global__ void router_kernel(const float* __restrict__ x,
                              const float* __restrict__ Wr, int N) {
    int gw   = (blockIdx.x * blockDim.x + threadIdx.x) >> 5;
    int lane = threadIdx.x & 31;
    if (gw >= N) return;
    const float* xr = x + (size_t)gw * CDIM;

    float acc[EXP];
#pragma unroll
    for (int e = 0; e < EXP; e++) acc[e] = 0.0f;

    for (int k = lane; k < CDIM; k += 32) {
        float xv = xr[k];
        const float4* w4 = reinterpret_cast<const float4*>(Wr + (size_t)k * EXP);
        float4 w0 = w4[0], w1 = w4[1];
        acc[0] += xv * w0.x; acc[1] += xv * w0.y;
        acc[2] += xv * w0.z; acc[3] += xv * w0.w;
        acc[4] += xv * w1.x; acc[5] += xv * w1.y;
        acc[6] += xv * w1.z; acc[7] += xv * w1.w;
    }
#pragma unroll
    for (int e = 0; e < EXP; e++) {
#pragma unroll
        for (int off = 16; off > 0; off >>= 1)
            acc[e] += __shfl_xor_sync(0xFFFFFFFFu, acc[e], off);
    }

    if (lane == 0) {
        float m = acc[0];
#pragma unroll
        for (int e = 1; e < EXP; e++) m = fmaxf(m, acc[e]);
        float p[EXP], s = 0.0f;
#pragma unroll
        for (int e = 0; e < EXP; e++) { p[e] = expf(acc[e] - m); s += p[e]; }
        float inv = 1.0f / s;
#pragma unroll
        for (int e = 0; e < EXP; e++) p[e] *= inv;

        int i1 = 0;
#pragma unroll
        for (int e = 1; e < EXP; e++) if (p[e] > p[i1]) i1 = e;
        int i2 = (i1 == 0) ? 1 : 0;
#pragma unroll
        for (int e = 0; e < EXP; e++)
            if (e != i1 && p[e] > p[i2]) i2 = e;

        float denom = p[i1] + p[i2] + 1e-9f;
        float w1 = p[i1] / denom;
        float w2 = p[i2] / denom;

        int s1 = atomicAdd(&d_fill[i1], 1);
        d_tok[i1 * MAXN + s1] = gw; d_wgt[i1 * MAXN + s1] = w1;
        int s2 = atomicAdd(&d_fill[i2], 1);
        d_tok[i2 * MAXN + s2] = gw; d_wgt[i2 * MAXN + s2] = w2;
    }
}

__global__ void offsets_kernel() {
    if (threadIdx.x == 0) {
        int o = 0;
        for (int e = 0; e < EXP; e++) { d_off[e] = o; o += d_fill[e]; }
    }
}

// ---------------------------------------------------------------------------
// tf32 MMA GEMM1: hbuf = gelu( gather(x) @ W1[e] + b1[e] )
// 128x128x16 block, 8 warps (2x4), warp 64x32, m16n8k8 tf32
// ---------------------------------------------------------------------------
__global__ void __launch_bounds__(256, 1)
gemm1_kernel(const float* __restrict__ x, const float* __restrict__ W1,
             const float* __restrict__ b1) {
    int e   = blockIdx.z;
    int cnt = d_fill[e];
    int m0  = blockIdx.x * BM;
    if (m0 >= cnt) return;
    int j0  = blockIdx.y * BN;

    __shared__ unsigned As[2][BM * AS_STRIDE];
    __shared__ unsigned Bs[2][BK * BS_STRIDE];

    int t = threadIdx.x, lane = t & 31, w = t >> 5;
    int wm = (w & 1) * 64, wn = (w >> 1) * 32;

    const float* W1e = W1 + (size_t)e * CDIM * HDIM;

    // ---- loader setup: 2 float4 per thread for A and for B ----
    const float* aptr[2]; int asmoff[2];
#pragma unroll
    for (int i = 0; i < 2; i++) {
        int idx = t + i * 256;
        int row = idx >> 2, c4 = idx & 3;
        int gm = m0 + row;
        int tok = (gm < cnt) ? d_tok[e * MAXN + gm] : -1;
        aptr[i]   = (tok >= 0) ? (x + (size_t)tok * CDIM + c4 * 4) : nullptr;
        asmoff[i] = row * AS_STRIDE + c4 * 4;
    }
    const float* bptr[2]; int bsmoff[2];
#pragma unroll
    for (int i = 0; i < 2; i++) {
        int idx = t + i * 256;
        int kr = idx >> 5, c4 = idx & 31;
        bptr[i]   = W1e + (size_t)kr * HDIM + j0 + c4 * 4;
        bsmoff[i] = kr * BS_STRIDE + c4 * 4;
    }

    float acc[4][4][4];
#pragma unroll
    for (int mt = 0; mt < 4; mt++)
#pragma unroll
        for (int nt = 0; nt < 4; nt++)
#pragma unroll
            for (int i = 0; i < 4; i++) acc[mt][nt][i] = 0.0f;

    // ---- preload tile 0 ----
    float4 ra[2], rb[2];
#pragma unroll
    for (int i = 0; i < 2; i++) {
        ra[i] = aptr[i] ? *reinterpret_cast<const float4*>(aptr[i])
                        : make_float4(0.f, 0.f, 0.f, 0.f);
        rb[i] = *reinterpret_cast<const float4*>(bptr[i]);
    }
#pragma unroll
    for (int i = 0; i < 2; i++) {
        unsigned* a = &As[0][asmoff[i]];
        a[0] = f2tf32(ra[i].x); a[1] = f2tf32(ra[i].y);
        a[2] = f2tf32(ra[i].z); a[3] = f2tf32(ra[i].w);
        unsigned* b = &Bs[0][bsmoff[i]];
        b[0] = f2tf32(rb[i].x); b[1] = f2tf32(rb[i].y);
        b[2] = f2tf32(rb[i].z); b[3] = f2tf32(rb[i].w);
    }
    __syncthreads();

    int p = 0;
    for (int k0 = 0; k0 < CDIM; k0 += BK) {
        bool not_last = (k0 + BK < CDIM);
        if (not_last) {
#pragma unroll
            for (int i = 0; i < 2; i++) {
                ra[i] = aptr[i] ? *reinterpret_cast<const float4*>(aptr[i] + k0 + BK)
                                : make_float4(0.f, 0.f, 0.f, 0.f);
                rb[i] = *reinterpret_cast<const float4*>(bptr[i] + (size_t)(k0 + BK) * HDIM);
            }
        }
        const unsigned* Ac = As[p];
        const unsigned* Bc = Bs[p];
#pragma unroll
        for (int ks = 0; ks < 2; ks++) {
            int kb = ks * 8 + (lane & 3);
            unsigned afr[4][4], bfr[4][2];
#pragma unroll
            for (int mt = 0; mt < 4; mt++) {
                int r0 = wm + mt * 16 + (lane >> 2);
                afr[mt][0] = Ac[r0 * AS_STRIDE + kb];
                afr[mt][1] = Ac[(r0 + 8) * AS_STRIDE + kb];
                afr[mt][2] = Ac[r0 * AS_STRIDE + kb + 4];
                afr[mt][3] = Ac[(r0 + 8) * AS_STRIDE + kb + 4];
            }
#pragma unroll
            for (int nt = 0; nt < 4; nt++) {
                int cN = wn + nt * 8 + (lane >> 2);
                bfr[nt][0] = Bc[kb * BS_STRIDE + cN];
                bfr[nt][1] = Bc[(kb + 4) * BS_STRIDE + cN];
            }
#pragma unroll
            for (int mt = 0; mt < 4; mt++)
#pragma unroll
                for (int nt = 0; nt < 4; nt++)
                    mma_tf32(acc[mt][nt], afr[mt], bfr[nt]);
        }
        if (not_last) {
            unsigned* an = As[p ^ 1];
            unsigned* bn = Bs[p ^ 1];
#pragma unroll
            for (int i = 0; i < 2; i++) {
                unsigned* a = &an[asmoff[i]];
                a[0] = f2tf32(ra[i].x); a[1] = f2tf32(ra[i].y);
                a[2] = f2tf32(ra[i].z); a[3] = f2tf32(ra[i].w);
                unsigned* b = &bn[bsmoff[i]];
                b[0] = f2tf32(rb[i].x); b[1] = f2tf32(rb[i].y);
                b[2] = f2tf32(rb[i].z); b[3] = f2tf32(rb[i].w);
            }
        }
        __syncthreads();
        p ^= 1;
    }

    // ---- epilogue: bias + gelu -> hbuf ----
    int off = d_off[e];
#pragma unroll
    for (int mt = 0; mt < 4; mt++) {
#pragma unroll
        for (int i2 = 0; i2 < 2; i2++) {     // row half (+0 / +8)
            int gm = m0 + wm + mt * 16 + (lane >> 2) + i2 * 8;
            if (gm >= cnt) continue;
            size_t rowbase = (size_t)(off + gm) * HDIM;
#pragma unroll
            for (int nt = 0; nt < 4; nt++) {
#pragma unroll
                for (int i1 = 0; i1 < 2; i1++) {  // col pair
                    int col = j0 + wn + nt * 8 + (lane & 3) * 2 + i1;
                    float v = acc[mt][nt][i2 * 2 + i1] + b1[e * HDIM + col];
                    v = 0.5f * v * (1.0f + erff(v * 0.70710678118654752f));
                    d_hbuf[rowbase + col] = v;
                }
            }
        }
    }
}

// ---------------------------------------------------------------------------
// tf32 MMA GEMM2: out[tok] += w * ( hbuf @ W2[e] + b2[e] )
// ---------------------------------------------------------------------------
__global__ void __launch_bounds__(256, 1)
gemm2_kernel(const float* __restrict__ W2, const float* __restrict__ b2,
             float* __restrict__ out) {
    int e   = blockIdx.z;
    int cnt = d_fill[e];
    int m0  = blockIdx.x * BM;
    if (m0 >= cnt) return;
    int j0  = blockIdx.y * BN;
    int off = d_off[e];

    __shared__ unsigned As[2][BM * AS_STRIDE];
    __shared__ unsigned Bs[2][BK * BS_STRIDE];

    int t = threadIdx.x, lane = t & 31, w = t >> 5;
    int wm = (w & 1) * 64, wn = (w >> 1) * 32;

    const float* W2e = W2 + (size_t)e * HDIM * CDIM;

    const float* aptr[2]; int asmoff[2];
#pragma unroll
    for (int i = 0; i < 2; i++) {
        int idx = t + i * 256;
        int row = idx >> 2, c4 = idx & 3;
        int gm = m0 + row;
        aptr[i]   = (gm < cnt) ? (d_hbuf + (size_t)(off + gm) * HDIM + c4 * 4) : nullptr;
        asmoff[i] = row * AS_STRIDE + c4 * 4;
    }
    const float* bptr[2]; int bsmoff[2];
#pragma unroll
    for (int i = 0; i < 2; i++) {
        int idx = t + i * 256;
        int kr = idx >> 5, c4 = idx & 31;
        bptr[i]   = W2e + (size_t)kr * CDIM + j0 + c4 * 4;
        bsmoff[i] = kr * BS_STRIDE + c4 * 4;
    }

    float acc[4][4][4];
#pragma unroll
    for (int mt = 0; mt < 4; mt++)
#pragma unroll
        for (int nt = 0; nt < 4; nt++)
#pragma unroll
            for (int i = 0; i < 4; i++) acc[mt][nt][i] = 0.0f;

    float4 ra[2], rb[2];
#pragma unroll
    for (int i = 0; i < 2; i++) {
        ra[i] = aptr[i] ? *reinterpret_cast<const float4*>(aptr[i])
                        : make_float4(0.f, 0.f, 0.f, 0.f);
        rb[i] = *reinterpret_cast<const float4*>(bptr[i]);
    }
#pragma unroll
    for (int i = 0; i < 2; i++) {
        unsigned* a = &As[0][asmoff[i]];
        a[0] = f2tf32(ra[i].x); a[1] = f2tf32(ra[i].y);
        a[2] = f2tf32(ra[i].z); a[3] = f2tf32(ra[i].w);
        unsigned* b = &Bs[0][bsmoff[i]];
        b[0] = f2tf32(rb[i].x); b[1] = f2tf32(rb[i].y);
        b[2] = f2tf32(rb[i].z); b[3] = f2tf32(rb[i].w);
    }
    __syncthreads();

    int p = 0;
    for (int k0 = 0; k0 < HDIM; k0 += BK) {
        bool not_last = (k0 + BK < HDIM);
        if (not_last) {
#pragma unroll
            for (int i = 0; i < 2; i++) {
                ra[i] = aptr[i] ? *reinterpret_cast<const float4*>(aptr[i] + k0 + BK)
                                : make_float4(0.f, 0.f, 0.f, 0.f);
                rb[i] = *reinterpret_cast<const float4*>(bptr[i] + (size_t)(k0 + BK) * CDIM);
            }
        }
        const unsigned* Ac = As[p];
        const unsigned* Bc = Bs[p];
#pragma unroll
        for (int ks = 0; ks < 2; ks++) {
            int kb = ks * 8 + (lane & 3);
            unsigned afr[4][4], bfr[4][2];
#pragma unroll
            for (int mt = 0; mt < 4; mt++) {
                int r0 = wm + mt * 16 + (lane >> 2);
                afr[mt][0] = Ac[r0 * AS_STRIDE + kb];
                afr[mt][1] = Ac[(r0 + 8) * AS_STRIDE + kb];
                afr[mt][2] = Ac[r0 * AS_STRIDE + kb + 4];
                afr[mt][3] = Ac[(r0 + 8) * AS_STRIDE + kb + 4];
            }
#pragma unroll
            for (int nt = 0; nt < 4; nt++) {
                int cN = wn + nt * 8 + (lane >> 2);
                bfr[nt][0] = Bc[kb * BS_STRIDE + cN];
                bfr[nt][1] = Bc[(kb + 4) * BS_STRIDE + cN];
            }
#pragma unroll
            for (int mt = 0; mt < 4; mt++)
#pragma unroll
                for (int nt = 0; nt < 4; nt++)
                    mma_tf32(acc[mt][nt], afr[mt], bfr[nt]);
        }
        if (not_last) {
            unsigned* an = As[p ^ 1];
            unsigned* bn = Bs[p ^ 1];
#pragma unroll
            for (int i = 0; i < 2; i++) {
                unsigned* a = &an[asmoff[i]];
                a[0] = f2tf32(ra[i].x); a[1] = f2tf32(ra[i].y);
                a[2] = f2tf32(ra[i].z); a[3] = f2tf32(ra[i].w);
                unsigned* b = &bn[bsmoff[i]];
                b[0] = f2tf32(rb[i].x); b[1] = f2tf32(rb[i].y);
                b[2] = f2tf32(rb[i].z); b[3] = f2tf32(rb[i].w);
            }
        }
        __syncthreads();
        p ^= 1;
    }

    // ---- epilogue: bias, weight, atomic scatter-add into out ----
#pragma unroll
    for (int mt = 0; mt < 4; mt++) {
#pragma unroll
        for (int i2 = 0; i2 < 2; i2++) {
            int gm = m0 + wm + mt * 16 + (lane >> 2) + i2 * 8;
            if (gm >= cnt) continue;
            int   tok = d_tok[e * MAXN + gm];
            float wgt = d_wgt[e * MAXN + gm];
            size_t obase = (size_t)tok * CDIM;
#pragma unroll
            for (int nt = 0; nt < 4; nt++) {
#pragma unroll
                for (int i1 = 0; i1 < 2; i1++) {
                    int col = j0 + wn + nt * 8 + (lane & 3) * 2 + i1;
                    float v = acc[mt][nt][i2 * 2 + i1] + b2[e * CDIM + col];
                    atomicAdd(&out[obase + col], wgt * v);
                }
            }
        }
    }
}

// ---------------------------------------------------------------------------
__global__ void util_kernel(float* __restrict__ out, int NC) {
    int e = threadIdx.x;
    if (e < EXP) {
        float tot = 0.0f;
        for (int j = 0; j < EXP; j++) tot += (float)d_fill[j];
        out[NC + e] = (float)d_fill[e] / (tot + 1e-9f);
    }
}

// ---------------------------------------------------------------------------
extern "C" void kernel_launch(void* const* d_in, const int* in_sizes, int n_in,
                              void* d_out, int out_size) {
    const float* x  = (const float*)d_in[0];
    const float* Wr = (const float*)d_in[1];
    const float* W1 = (const float*)d_in[2];
    const float* b1 = (const float*)d_in[3];
    const float* W2 = (const float*)d_in[4];
    const float* b2 = (const float*)d_in[5];
    float* out = (float*)d_out;

    int N  = in_sizes[0] / CDIM;   // 8192
    int NC = N * CDIM;

    zero_kernel<<<(NC + 255) / 256, 256>>>(out, NC);
    router_kernel<<<(N + 7) / 8, 256>>>(x, Wr, N);
    offsets_kernel<<<1, 32>>>();

    dim3 g1((N + BM - 1) / BM, HDIM / BN, EXP);
    gemm1_kernel<<<g1, 256>>>(x, W1, b1);

    dim3 g2((N + BM - 1) / BM, CDIM / BN, EXP);
    gemm2_kernel<<<g2, 256>>>(W2, b2, out);

    util_kernel<<<1, 32>>>(out, NC);
}

// round 3
// speedup vs baseline: 4.6934x; 2.2478x over previous
#include <cuda_runtime.h>
#include <cuda_fp16.h>
#include <math.h>

#define CDIM 768
#define EXP 8
#define HDIM 3072
#define MAXN 8192

#define BM 128
#define BN 128
#define BK 32
#define STRD 20            // half2-unit row stride: (20*r + q) % 32 is a permutation

// ---- scratch (device globals; no cudaMalloc allowed) ----
__device__ int    d_fill[EXP];
__device__ int    d_off[EXP];
__device__ int    d_tok[EXP * MAXN];
__device__ float  d_wgt[EXP * MAXN];
__device__ __half d_hbufh[(size_t)2 * MAXN * HDIM];   // 2N x H fp16 (~100 MB)

__device__ __forceinline__ void mma_f16(float* c, const unsigned* a, const unsigned* b) {
    asm volatile(
        "mma.sync.aligned.m16n8k16.row.col.f32.f16.f16.f32 "
        "{%0,%1,%2,%3}, {%4,%5,%6,%7}, {%8,%9}, {%0,%1,%2,%3};"
        : "+f"(c[0]), "+f"(c[1]), "+f"(c[2]), "+f"(c[3])
        : "r"(a[0]), "r"(a[1]), "r"(a[2]), "r"(a[3]), "r"(b[0]), "r"(b[1]));
}

__device__ __forceinline__ unsigned pack2(float lo, float hi) {
    __half2 h = __floats2half2_rn(lo, hi);
    return *reinterpret_cast<unsigned*>(&h);
}

// ---------------------------------------------------------------------------
__global__ void zero_kernel(float* __restrict__ out, int total) {
    int idx = blockIdx.x * blockDim.x + threadIdx.x;
    if (idx < total) out[idx] = 0.0f;
    if (blockIdx.x == 0 && threadIdx.x < EXP) d_fill[threadIdx.x] = 0;
}

// ---------------------------------------------------------------------------
// router: 1 warp per token
// ---------------------------------------------------------------------------
__global__ void router_kernel(const float* __restrict__ x,
                              const float* __restrict__ Wr, int N) {
    int gw   = (blockIdx.x * blockDim.x + threadIdx.x) >> 5;
    int lane = threadIdx.x & 31;
    if (gw >= N) return;
    const float* xr = x + (size_t)gw * CDIM;

    float acc[EXP];
#pragma unroll
    for (int e = 0; e < EXP; e++) acc[e] = 0.0f;

    for (int k = lane; k < CDIM; k += 32) {
        float xv = xr[k];
        const float4* w4 = reinterpret_cast<const float4*>(Wr + (size_t)k * EXP);
        float4 w0 = w4[0], w1 = w4[1];
        acc[0] += xv * w0.x; acc[1] += xv * w0.y;
        acc[2] += xv * w0.z; acc[3] += xv * w0.w;
        acc[4] += xv * w1.x; acc[5] += xv * w1.y;
        acc[6] += xv * w1.z; acc[7] += xv * w1.w;
    }
#pragma unroll
    for (int e = 0; e < EXP; e++) {
#pragma unroll
        for (int off = 16; off > 0; off >>= 1)
            acc[e] += __shfl_xor_sync(0xFFFFFFFFu, acc[e], off);
    }

    if (lane == 0) {
        float m = acc[0];
#pragma unroll
        for (int e = 1; e < EXP; e++) m = fmaxf(m, acc[e]);
        float p[EXP], s = 0.0f;
#pragma unroll
        for (int e = 0; e < EXP; e++) { p[e] = expf(acc[e] - m); s += p[e]; }
        float inv = 1.0f / s;
#pragma unroll
        for (int e = 0; e < EXP; e++) p[e] *= inv;

        int i1 = 0;
#pragma unroll
        for (int e = 1; e < EXP; e++) if (p[e] > p[i1]) i1 = e;
        int i2 = (i1 == 0) ? 1 : 0;
#pragma unroll
        for (int e = 0; e < EXP; e++)
            if (e != i1 && p[e] > p[i2]) i2 = e;

        float denom = p[i1] + p[i2] + 1e-9f;
        float w1 = p[i1] / denom;
        float w2 = p[i2] / denom;

        int s1 = atomicAdd(&d_fill[i1], 1);
        d_tok[i1 * MAXN + s1] = gw; d_wgt[i1 * MAXN + s1] = w1;
        int s2 = atomicAdd(&d_fill[i2], 1);
        d_tok[i2 * MAXN + s2] = gw; d_wgt[i2 * MAXN + s2] = w2;
    }
}

__global__ void offsets_kernel() {
    if (threadIdx.x == 0) {
        int o = 0;
        for (int e = 0; e < EXP; e++) { d_off[e] = o; o += d_fill[e]; }
    }
}

// ---------------------------------------------------------------------------
// fp16 MMA GEMM1: hbufh = gelu( gather(x) @ W1[e] + b1[e] )
// 128x128x32 tile, 512 thr (16 warps 4x4, warp 32x32), m16n8k16
// ---------------------------------------------------------------------------
__global__ void __launch_bounds__(512, 2)
gemm1_kernel(const float* __restrict__ x, const float* __restrict__ W1,
             const float* __restrict__ b1) {
    int e   = blockIdx.z;
    int cnt = d_fill[e];
    int m0  = blockIdx.x * BM;
    if (m0 >= cnt) return;
    int j0  = blockIdx.y * BN;

    __shared__ __half2 As2[2][BM * STRD];
    __shared__ __half2 Bs2[2][BN * STRD];

    int t = threadIdx.x, lane = t & 31, w = t >> 5;
    int wm = (w & 3) * 32, wn = (w >> 2) * 32;

    const float* W1e = W1 + (size_t)e * CDIM * HDIM;

    // A loader: row = t>>2 (128 rows), k-chunk of 8 at (t&3)*8
    int arow = t >> 2, ac4 = t & 3;
    int gmA  = m0 + arow;
    int tokA = (gmA < cnt) ? d_tok[e * MAXN + gmA] : -1;
    const float* aptr = (tokA >= 0) ? (x + (size_t)tokA * CDIM + ac4 * 8) : nullptr;
    int asoff = arow * STRD + ac4 * 4;
    // B loader: n = t&127, k-chunk of 8 at (t>>7)*8
    int bn = t & 127, bkg = t >> 7;
    const float* bptr = W1e + (size_t)(bkg * 8) * HDIM + j0 + bn;
    int bsoff = bn * STRD + bkg * 4;

    float acc[2][4][4];
#pragma unroll
    for (int mt = 0; mt < 2; mt++)
#pragma unroll
        for (int nt = 0; nt < 4; nt++)
#pragma unroll
            for (int i = 0; i < 4; i++) acc[mt][nt][i] = 0.0f;

    float ra[8], rb[8];
    // preload tile 0
#pragma unroll
    for (int i = 0; i < 8; i++) rb[i] = bptr[(size_t)i * HDIM];
    if (aptr) {
        float4 a0 = *reinterpret_cast<const float4*>(aptr);
        float4 a1 = *reinterpret_cast<const float4*>(aptr + 4);
        ra[0]=a0.x; ra[1]=a0.y; ra[2]=a0.z; ra[3]=a0.w;
        ra[4]=a1.x; ra[5]=a1.y; ra[6]=a1.z; ra[7]=a1.w;
    } else {
#pragma unroll
        for (int i = 0; i < 8; i++) ra[i] = 0.0f;
    }
    {
        uint4 av = make_uint4(pack2(ra[0],ra[1]), pack2(ra[2],ra[3]),
                              pack2(ra[4],ra[5]), pack2(ra[6],ra[7]));
        uint4 bv = make_uint4(pack2(rb[0],rb[1]), pack2(rb[2],rb[3]),
                              pack2(rb[4],rb[5]), pack2(rb[6],rb[7]));
        *reinterpret_cast<uint4*>(&As2[0][asoff]) = av;
        *reinterpret_cast<uint4*>(&Bs2[0][bsoff]) = bv;
    }
    __syncthreads();

    int p = 0;
    for (int k0 = 0; k0 < CDIM; k0 += BK) {
        bool not_last = (k0 + BK < CDIM);
        if (not_last) {
#pragma unroll
            for (int i = 0; i < 8; i++)
                rb[i] = bptr[(size_t)(k0 + BK + i) * HDIM];
            if (aptr) {
                float4 a0 = *reinterpret_cast<const float4*>(aptr + k0 + BK);
                float4 a1 = *reinterpret_cast<const float4*>(aptr + k0 + BK + 4);
                ra[0]=a0.x; ra[1]=a0.y; ra[2]=a0.z; ra[3]=a0.w;
                ra[4]=a1.x; ra[5]=a1.y; ra[6]=a1.z; ra[7]=a1.w;
            }
        }
        const unsigned* Ac = reinterpret_cast<const unsigned*>(As2[p]);
        const unsigned* Bc = reinterpret_cast<const unsigned*>(Bs2[p]);
#pragma unroll
        for (int ks = 0; ks < 2; ks++) {
            int q = (lane & 3) + ks * 8;
            unsigned afr[2][4], bfr[4][2];
#pragma unroll
            for (int mt = 0; mt < 2; mt++) {
                int r0 = wm + mt * 16 + (lane >> 2);
                afr[mt][0] = Ac[r0 * STRD + q];
                afr[mt][1] = Ac[(r0 + 8) * STRD + q];
                afr[mt][2] = Ac[r0 * STRD + q + 4];
                afr[mt][3] = Ac[(r0 + 8) * STRD + q + 4];
            }
#pragma unroll
            for (int nt = 0; nt < 4; nt++) {
                int nn = wn + nt * 8 + (lane >> 2);
                bfr[nt][0] = Bc[nn * STRD + q];
                bfr[nt][1] = Bc[nn * STRD + q + 4];
            }
#pragma unroll
            for (int mt = 0; mt < 2; mt++)
#pragma unroll
                for (int nt = 0; nt < 4; nt++)
                    mma_f16(acc[mt][nt], afr[mt], bfr[nt]);
        }
        if (not_last) {
            uint4 av = make_uint4(pack2(ra[0],ra[1]), pack2(ra[2],ra[3]),
                                  pack2(ra[4],ra[5]), pack2(ra[6],ra[7]));
            uint4 bv = make_uint4(pack2(rb[0],rb[1]), pack2(rb[2],rb[3]),
                                  pack2(rb[4],rb[5]), pack2(rb[6],rb[7]));
            *reinterpret_cast<uint4*>(&As2[p ^ 1][asoff]) = av;
            *reinterpret_cast<uint4*>(&Bs2[p ^ 1][bsoff]) = bv;
        }
        __syncthreads();
        p ^= 1;
    }

    // epilogue: bias + gelu -> hbufh (half2 stores)
    int off = d_off[e];
    __half2* h2 = reinterpret_cast<__half2*>(d_hbufh);
#pragma unroll
    for (int mt = 0; mt < 2; mt++) {
#pragma unroll
        for (int i2 = 0; i2 < 2; i2++) {
            int gm = m0 + wm + mt * 16 + (lane >> 2) + i2 * 8;
            if (gm >= cnt) continue;
            size_t rowbase = (size_t)(off + gm) * HDIM;
#pragma unroll
            for (int nt = 0; nt < 4; nt++) {
                int col = j0 + wn + nt * 8 + (lane & 3) * 2;
                float v0 = acc[mt][nt][i2 * 2 + 0] + b1[e * HDIM + col];
                float v1 = acc[mt][nt][i2 * 2 + 1] + b1[e * HDIM + col + 1];
                v0 = 0.5f * v0 * (1.0f + erff(v0 * 0.70710678118654752f));
                v1 = 0.5f * v1 * (1.0f + erff(v1 * 0.70710678118654752f));
                h2[(rowbase + col) >> 1] = __floats2half2_rn(v0, v1);
            }
        }
    }
}

// ---------------------------------------------------------------------------
// fp16 MMA GEMM2: out[tok] += w * ( hbufh @ W2[e] + b2[e] )
// ---------------------------------------------------------------------------
__global__ void __launch_bounds__(512, 2)
gemm2_kernel(const float* __restrict__ W2, const float* __restrict__ b2,
             float* __restrict__ out) {
    int e   = blockIdx.z;
    int cnt = d_fill[e];
    int m0  = blockIdx.x * BM;
    if (m0 >= cnt) return;
    int j0  = blockIdx.y * BN;
    int off = d_off[e];

    __shared__ __half2 As2[2][BM * STRD];
    __shared__ __half2 Bs2[2][BN * STRD];

    int t = threadIdx.x, lane = t & 31, w = t >> 5;
    int wm = (w & 3) * 32, wn = (w >> 2) * 32;

    const float* W2e = W2 + (size_t)e * HDIM * CDIM;

    // A loader: 8 halves (uint4) per thread per tile
    int arow = t >> 2, ac4 = t & 3;
    int gmA  = m0 + arow;
    const __half* aptr = (gmA < cnt)
        ? (d_hbufh + (size_t)(off + gmA) * HDIM + ac4 * 8) : nullptr;
    int asoff = arow * STRD + ac4 * 4;
    // B loader
    int bn = t & 127, bkg = t >> 7;
    const float* bptr = W2e + (size_t)(bkg * 8) * CDIM + j0 + bn;
    int bsoff = bn * STRD + bkg * 4;

    float acc[2][4][4];
#pragma unroll
    for (int mt = 0; mt < 2; mt++)
#pragma unroll
        for (int nt = 0; nt < 4; nt++)
#pragma unroll
            for (int i = 0; i < 4; i++) acc[mt][nt][i] = 0.0f;

    uint4 rav; float rb[8];
#pragma unroll
    for (int i = 0; i < 8; i++) rb[i] = bptr[(size_t)i * CDIM];
    rav = aptr ? *reinterpret_cast<const uint4*>(aptr) : make_uint4(0, 0, 0, 0);
    {
        uint4 bv = make_uint4(pack2(rb[0],rb[1]), pack2(rb[2],rb[3]),
                              pack2(rb[4],rb[5]), pack2(rb[6],rb[7]));
        *reinterpret_cast<uint4*>(&As2[0][asoff]) = rav;
        *reinterpret_cast<uint4*>(&Bs2[0][bsoff]) = bv;
    }
    __syncthreads();

    int p = 0;
    for (int k0 = 0; k0 < HDIM; k0 += BK) {
        bool not_last = (k0 + BK < HDIM);
        if (not_last) {
#pragma unroll
            for (int i = 0; i < 8; i++)
                rb[i] = bptr[(size_t)(k0 + BK + i) * CDIM];
            if (aptr)
                rav = *reinterpret_cast<const uint4*>(aptr + k0 + BK);
        }
        const unsigned* Ac = reinterpret_cast<const unsigned*>(As2[p]);
        const unsigned* Bc = reinterpret_cast<const unsigned*>(Bs2[p]);
#pragma unroll
        for (int ks = 0; ks < 2; ks++) {
            int q = (lane & 3) + ks * 8;
            unsigned afr[2][4], bfr[4][2];
#pragma unroll
            for (int mt = 0; mt < 2; mt++) {
                int r0 = wm + mt * 16 + (lane >> 2);
                afr[mt][0] = Ac[r0 * STRD + q];
                afr[mt][1] = Ac[(r0 + 8) * STRD + q];
                afr[mt][2] = Ac[r0 * STRD + q + 4];
                afr[mt][3] = Ac[(r0 + 8) * STRD + q + 4];
            }
#pragma unroll
            for (int nt = 0; nt < 4; nt++) {
                int nn = wn + nt * 8 + (lane >> 2);
                bfr[nt][0] = Bc[nn * STRD + q];
                bfr[nt][1] = Bc[nn * STRD + q + 4];
            }
#pragma unroll
            for (int mt = 0; mt < 2; mt++)
#pragma unroll
                for (int nt = 0; nt < 4; nt++)
                    mma_f16(acc[mt][nt], afr[mt], bfr[nt]);
        }
        if (not_last) {
            uint4 bv = make_uint4(pack2(rb[0],rb[1]), pack2(rb[2],rb[3]),
                                  pack2(rb[4],rb[5]), pack2(rb[6],rb[7]));
            *reinterpret_cast<uint4*>(&As2[p ^ 1][asoff]) = rav;
            *reinterpret_cast<uint4*>(&Bs2[p ^ 1][bsoff]) = bv;
        }
        __syncthreads();
        p ^= 1;
    }

    // epilogue: bias, weight, atomic scatter-add into out
#pragma unroll
    for (int mt = 0; mt < 2; mt++) {
#pragma unroll
        for (int i2 = 0; i2 < 2; i2++) {
            int gm = m0 + wm + mt * 16 + (lane >> 2) + i2 * 8;
            if (gm >= cnt) continue;
            int   tok = d_tok[e * MAXN + gm];
            float wgt = d_wgt[e * MAXN + gm];
            size_t obase = (size_t)tok * CDIM;
#pragma unroll
            for (int nt = 0; nt < 4; nt++) {
                int col = j0 + wn + nt * 8 + (lane & 3) * 2;
                float v0 = acc[mt][nt][i2 * 2 + 0] + b2[e * CDIM + col];
                float v1 = acc[mt][nt][i2 * 2 + 1] + b2[e * CDIM + col + 1];
                atomicAdd(&out[obase + col],     wgt * v0);
                atomicAdd(&out[obase + col + 1], wgt * v1);
            }
        }
    }
}

// ---------------------------------------------------------------------------
__global__ void util_kernel(float* __restrict__ out, int NC) {
    int e = threadIdx.x;
    if (e < EXP) {
        float tot = 0.0f;
        for (int j = 0; j < EXP; j++) tot += (float)d_fill[j];
        out[NC + e] = (float)d_fill[e] / (tot + 1e-9f);
    }
}

// ---------------------------------------------------------------------------
extern "C" void kernel_launch(void* const* d_in, const int* in_sizes, int n_in,
                              void* d_out, int out_size) {
    const float* x  = (const float*)d_in[0];
    const float* Wr = (const float*)d_in[1];
    const float* W1 = (const float*)d_in[2];
    const float* b1 = (const float*)d_in[3];
    const float* W2 = (const float*)d_in[4];
    const float* b2 = (const float*)d_in[5];
    float* out = (float*)d_out;

    int N  = in_sizes[0] / CDIM;   // 8192
    int NC = N * CDIM;

    zero_kernel<<<(NC + 255) / 256, 256>>>(out, NC);
    router_kernel<<<(N + 7) / 8, 256>>>(x, Wr, N);
    offsets_kernel<<<1, 32>>>();

    dim3 g1((N + BM - 1) / BM, HDIM / BN, EXP);
    gemm1_kernel<<<g1, 512>>>(x, W1, b1);

    dim3 g2((N + BM - 1) / BM, CDIM / BN, EXP);
    gemm2_kernel<<<g2, 512>>>(W2, b2, out);

    util_kernel<<<1, 32>>>(out, NC);
}

// round 5
// speedup vs baseline: 7.0730x; 1.5070x over previous
#include <cuda_runtime.h>
#include <cuda_fp16.h>
#include <math.h>

#define CDIM 768
#define EXP 8
#define HDIM 3072
#define MAXN 8192

// ---- scratch (device globals; no cudaMalloc allowed) ----
__device__ int    d_fill[EXP];
__device__ int    d_off[EXP];
__device__ int    d_tok[EXP * MAXN];
__device__ float  d_wgt[EXP * MAXN];
__device__ __half d_xh[(size_t)MAXN * CDIM];           // x fp16 [N,C]
__device__ __half d_w1h[(size_t)EXP * CDIM * HDIM];    // W1 fp16 [e][C][H] (k-major rows of n)
__device__ __half d_w2h[(size_t)EXP * HDIM * CDIM];    // W2 fp16 [e][H][C]
__device__ __half d_hbufh[(size_t)2 * MAXN * HDIM];    // hidden fp16

__device__ __forceinline__ unsigned smem_u32(const void* p) {
    unsigned a;
    asm("{ .reg .u64 t; cvta.to.shared.u64 t, %1; cvt.u32.u64 %0, t; }"
        : "=r"(a) : "l"(p));
    return a;
}

__device__ __forceinline__ void mma_f16(float* c, const unsigned* a, const unsigned* b) {
    asm volatile(
        "mma.sync.aligned.m16n8k16.row.col.f32.f16.f16.f32 "
        "{%0,%1,%2,%3}, {%4,%5,%6,%7}, {%8,%9}, {%0,%1,%2,%3};"
        : "+f"(c[0]), "+f"(c[1]), "+f"(c[2]), "+f"(c[3])
        : "r"(a[0]), "r"(a[1]), "r"(a[2]), "r"(a[3]), "r"(b[0]), "r"(b[1]));
}

__device__ __forceinline__ void ldsm4(unsigned* r, unsigned addr) {
    asm volatile("ldmatrix.sync.aligned.m8n8.x4.shared.b16 {%0,%1,%2,%3}, [%4];"
                 : "=r"(r[0]), "=r"(r[1]), "=r"(r[2]), "=r"(r[3]) : "r"(addr));
}
__device__ __forceinline__ void ldsm4t(unsigned* r, unsigned addr) {
    asm volatile("ldmatrix.sync.aligned.m8n8.x4.trans.shared.b16 {%0,%1,%2,%3}, [%4];"
                 : "=r"(r[0]), "=r"(r[1]), "=r"(r[2]), "=r"(r[3]) : "r"(addr));
}

// ---------------------------------------------------------------------------
__global__ void zero_kernel(float* __restrict__ out, int total) {
    int idx = blockIdx.x * blockDim.x + threadIdx.x;
    if (idx < total) out[idx] = 0.0f;
    if (blockIdx.x == 0 && threadIdx.x < EXP) d_fill[threadIdx.x] = 0;
}

// fp32 -> fp16 elementwise (vectorized), n4 = count/4
__global__ void cvt_half_kernel(const float* __restrict__ in, __half* __restrict__ outp,
                                long n4) {
    long i = (long)blockIdx.x * blockDim.x + threadIdx.x;
    if (i < n4) {
        float4 v = reinterpret_cast<const float4*>(in)[i];
        __half2* o = reinterpret_cast<__half2*>(outp) + i * 2;
        o[0] = __floats2half2_rn(v.x, v.y);
        o[1] = __floats2half2_rn(v.z, v.w);
    }
}

// ---------------------------------------------------------------------------
// router: 1 warp per token
// ---------------------------------------------------------------------------
__global__ void router_kernel(const float* __restrict__ x,
                              const float* __restrict__ Wr, int N) {
    int gw   = (blockIdx.x * blockDim.x + threadIdx.x) >> 5;
    int lane = threadIdx.x & 31;
    if (gw >= N) return;
    const float* xr = x + (size_t)gw * CDIM;

    float acc[EXP];
#pragma unroll
    for (int e = 0; e < EXP; e++) acc[e] = 0.0f;
    for (int k = lane; k < CDIM; k += 32) {
        float xv = xr[k];
        const float4* w4 = reinterpret_cast<const float4*>(Wr + (size_t)k * EXP);
        float4 w0 = w4[0], w1 = w4[1];
        acc[0] += xv * w0.x; acc[1] += xv * w0.y;
        acc[2] += xv * w0.z; acc[3] += xv * w0.w;
        acc[4] += xv * w1.x; acc[5] += xv * w1.y;
        acc[6] += xv * w1.z; acc[7] += xv * w1.w;
    }
#pragma unroll
    for (int e = 0; e < EXP; e++)
#pragma unroll
        for (int off = 16; off > 0; off >>= 1)
            acc[e] += __shfl_xor_sync(0xFFFFFFFFu, acc[e], off);

    if (lane == 0) {
        float m = acc[0];
#pragma unroll
        for (int e = 1; e < EXP; e++) m = fmaxf(m, acc[e]);
        float p[EXP], s = 0.0f;
#pragma unroll
        for (int e = 0; e < EXP; e++) { p[e] = expf(acc[e] - m); s += p[e]; }
        float inv = 1.0f / s;
#pragma unroll
        for (int e = 0; e < EXP; e++) p[e] *= inv;
        int i1 = 0;
#pragma unroll
        for (int e = 1; e < EXP; e++) if (p[e] > p[i1]) i1 = e;
        int i2 = (i1 == 0) ? 1 : 0;
#pragma unroll
        for (int e = 0; e < EXP; e++)
            if (e != i1 && p[e] > p[i2]) i2 = e;
        float denom = p[i1] + p[i2] + 1e-9f;
        float w1 = p[i1] / denom, w2 = p[i2] / denom;
        int s1 = atomicAdd(&d_fill[i1], 1);
        d_tok[i1 * MAXN + s1] = gw; d_wgt[i1 * MAXN + s1] = w1;
        int s2 = atomicAdd(&d_fill[i2], 1);
        d_tok[i2 * MAXN + s2] = gw; d_wgt[i2 * MAXN + s2] = w2;
    }
}

__global__ void offsets_kernel() {
    if (threadIdx.x == 0) {
        int o = 0;
        for (int e = 0; e < EXP; e++) { d_off[e] = o; o += d_fill[e]; }
    }
}

// ---------------------------------------------------------------------------
// fp16 mma.sync GEMM, CTA tile 128x256, BK=64, 256 thr, 8 warps (2m x 4n),
// warp tile 64x64, ldmatrix fragments, cp.async double buffer.
// smem: [0:512) tok, [512:1024) wgt, [1024) A0(16K) A1(16K) B0(32K) B1(32K)
// A smem: [m][64] halves, 128B rows, chunk swizzle  c ^= (row&7)
// B smem: [k][256] halves, 512B rows, chunk swizzle c ^= (row&7)
// MODE 0: A = gathered x rows -> gelu -> hbuf ;  MODE 1: A = hbuf -> scatter out
// ---------------------------------------------------------------------------
#define GSMEM 99328

template<int KD, int ND, int MODE>
__global__ void __launch_bounds__(256)
moe_gemm(const __half* __restrict__ Amat, const __half* __restrict__ Bmat,
         const float* __restrict__ bias, float* __restrict__ outp) {
    constexpr int ITERS = KD / 64;

    extern __shared__ char smem[];
    int*   stok = reinterpret_cast<int*>(smem);
    float* swgt = reinterpret_cast<float*>(smem + 512);
    const unsigned sA = smem_u32(smem + 1024);          // 2 x 16384
    const unsigned sB = sA + 32768;                     // 2 x 32768

    const int e   = blockIdx.z;
    const int cnt = d_fill[e];
    const int m0  = blockIdx.x * 128;
    if (m0 >= cnt) return;
    const int j0  = blockIdx.y * 256;
    const int off = d_off[e];
    const int tid = threadIdx.x;
    const int lane = tid & 31, w = tid >> 5;
    const int wm = (w & 1) * 64, wn = (w >> 1) * 64;

    if (tid < 128) {
        int gm = m0 + tid;
        stok[tid] = (gm < cnt) ? d_tok[e * MAXN + gm] : -1;
        swgt[tid] = (gm < cnt && MODE == 1) ? d_wgt[e * MAXN + gm] : 0.0f;
    }
    __syncthreads();

    // ---- cp.async slot setup: A 4 chunks (16B), B 8 chunks per thread ----
    const __half* agp[4]; unsigned aso[4], asz[4];
#pragma unroll
    for (int t = 0; t < 4; t++) {
        int idx = tid + t * 256, row = idx >> 3, c = idx & 7;
        bool ok; size_t base;
        if (MODE == 0) { int tk = stok[row]; ok = (tk >= 0); base = ok ? (size_t)tk * KD : 0; }
        else           { int gm = m0 + row;  ok = (gm < cnt); base = ok ? (size_t)(off + gm) * KD : 0; }
        agp[t] = Amat + base + c * 8;
        asz[t] = ok ? 16u : 0u;
        aso[t] = row * 128 + ((c ^ (row & 7)) * 16);
    }
    const __half* bbase = Bmat + (size_t)e * CDIM * HDIM + j0;
    int bgo[8]; unsigned bso[8];
#pragma unroll
    for (int t = 0; t < 8; t++) {
        int idx = tid + t * 256, row = idx >> 5, c = idx & 31;
        bgo[t] = row * ND + c * 8;
        bso[t] = row * 512 + ((c ^ (row & 7)) * 16);
    }

    auto load_tile = [&](int p, int k0) {
        unsigned Ab = sA + p * 16384, Bb = sB + p * 32768;
#pragma unroll
        for (int t = 0; t < 4; t++)
            asm volatile("cp.async.cg.shared.global [%0], [%1], 16, %2;"
                         :: "r"(Ab + aso[t]), "l"(agp[t] + k0), "r"(asz[t]) : "memory");
        const __half* bsrc = bbase + (size_t)k0 * ND;
#pragma unroll
        for (int t = 0; t < 8; t++)
            asm volatile("cp.async.cg.shared.global [%0], [%1], 16;"
                         :: "r"(Bb + bso[t]), "l"(bsrc + bgo[t]) : "memory");
        asm volatile("cp.async.commit_group;" ::: "memory");
    };

    float acc[4][8][4];
#pragma unroll
    for (int mt = 0; mt < 4; mt++)
#pragma unroll
        for (int nt = 0; nt < 8; nt++)
#pragma unroll
            for (int i = 0; i < 4; i++) acc[mt][nt][i] = 0.0f;

    const int rsel = (lane & 7) | (lane & 8);    // 0..15 row selector
    const int kh   = (lane >> 4) & 1;            // k/ n half selector
    const int l7   = lane & 7;

    load_tile(0, 0);

    for (int i = 0; i < ITERS; i++) {
        const int p = i & 1;
        if (i + 1 < ITERS) {
            load_tile((i + 1) & 1, (i + 1) * 64);
            asm volatile("cp.async.wait_group 1;" ::: "memory");
        } else {
            asm volatile("cp.async.wait_group 0;" ::: "memory");
        }
        __syncthreads();

        const unsigned Ab = sA + p * 16384, Bb = sB + p * 32768;
#pragma unroll
        for (int ks = 0; ks < 4; ks++) {
            unsigned afr[4][4];
#pragma unroll
            for (int mt = 0; mt < 4; mt++) {
                unsigned ad = Ab + (wm + mt * 16 + rsel) * 128
                            + (((ks * 2 + kh) ^ l7) * 16);
                ldsm4(afr[mt], ad);
            }
            unsigned bfr[8][2];
#pragma unroll
            for (int bt = 0; bt < 4; bt++) {
                int krow = ks * 16 + rsel;
                unsigned bd = Bb + krow * 512
                            + ((((wn >> 3) + bt * 2 + kh) ^ l7) * 16);
                unsigned r[4];
                ldsm4t(r, bd);
                bfr[bt * 2][0] = r[0];     bfr[bt * 2][1] = r[1];
                bfr[bt * 2 + 1][0] = r[2]; bfr[bt * 2 + 1][1] = r[3];
            }
#pragma unroll
            for (int mt = 0; mt < 4; mt++)
#pragma unroll
                for (int nt = 0; nt < 8; nt++)
                    mma_f16(acc[mt][nt], afr[mt], bfr[nt]);
        }
        __syncthreads();
    }

    // ---- epilogue ----
#pragma unroll
    for (int mt = 0; mt < 4; mt++) {
#pragma unroll
        for (int half = 0; half < 2; half++) {
            int lrow = wm + mt * 16 + (lane >> 2) + half * 8;
            int gm   = m0 + lrow;
            if (gm >= cnt) continue;
            if (MODE == 0) {
                __half* hrow = d_hbufh + (size_t)(off + gm) * HDIM;
#pragma unroll
                for (int nt = 0; nt < 8; nt++) {
                    int col = j0 + wn + nt * 8 + (lane & 3) * 2;
                    float v0 = acc[mt][nt][half * 2 + 0] + bias[(size_t)e * ND + col];
                    float v1 = acc[mt][nt][half * 2 + 1] + bias[(size_t)e * ND + col + 1];
                    v0 = 0.5f * v0 * (1.0f + erff(v0 * 0.70710678118654752f));
                    v1 = 0.5f * v1 * (1.0f + erff(v1 * 0.70710678118654752f));
                    *reinterpret_cast<__half2*>(hrow + col) = __floats2half2_rn(v0, v1);
                }
            } else {
                int   tok = stok[lrow];
                float wgt = swgt[lrow];
                float* orow = outp + (size_t)tok * CDIM;
#pragma unroll
                for (int nt = 0; nt < 8; nt++) {
                    int col = j0 + wn + nt * 8 + (lane & 3) * 2;
                    float v0 = acc[mt][nt][half * 2 + 0] + bias[(size_t)e * ND + col];
                    float v1 = acc[mt][nt][half * 2 + 1] + bias[(size_t)e * ND + col + 1];
                    atomicAdd(&orow[col],     wgt * v0);
                    atomicAdd(&orow[col + 1], wgt * v1);
                }
            }
        }
    }
}

// ---------------------------------------------------------------------------
__global__ void util_kernel(float* __restrict__ out, int NC) {
    int e = threadIdx.x;
    if (e < EXP) {
        float tot = 0.0f;
        for (int j = 0; j < EXP; j++) tot += (float)d_fill[j];
        out[NC + e] = (float)d_fill[e] / (tot + 1e-9f);
    }
}

// ---------------------------------------------------------------------------
extern "C" void kernel_launch(void* const* d_in, const int* in_sizes, int n_in,
                              void* d_out, int out_size) {
    const float* x  = (const float*)d_in[0];
    const float* Wr = (const float*)d_in[1];
    const float* W1 = (const float*)d_in[2];
    const float* b1 = (const float*)d_in[3];
    const float* W2 = (const float*)d_in[4];
    const float* b2 = (const float*)d_in[5];
    float* out = (float*)d_out;

    int N  = in_sizes[0] / CDIM;   // 8192
    int NC = N * CDIM;

    static int init_done = 0;
    if (!init_done) {
        cudaFuncSetAttribute(moe_gemm<CDIM, HDIM, 0>,
                             cudaFuncAttributeMaxDynamicSharedMemorySize, GSMEM);
        cudaFuncSetAttribute(moe_gemm<HDIM, CDIM, 1>,
                             cudaFuncAttributeMaxDynamicSharedMemorySize, GSMEM);
        init_done = 1;
    }

    __half *xh, *w1h, *w2h, *hb;
    cudaGetSymbolAddress((void**)&xh,  d_xh);
    cudaGetSymbolAddress((void**)&w1h, d_w1h);
    cudaGetSymbolAddress((void**)&w2h, d_w2h);
    cudaGetSymbolAddress((void**)&hb,  d_hbufh);

    zero_kernel<<<(NC + 255) / 256, 256>>>(out, NC);
    cvt_half_kernel<<<(NC / 4 + 255) / 256, 256>>>(x, xh, NC / 4);
    {
        long nw = (long)EXP * CDIM * HDIM / 4;
        cvt_half_kernel<<<(int)((nw + 255) / 256), 256>>>(W1, w1h, nw);
        cvt_half_kernel<<<(int)((nw + 255) / 256), 256>>>(W2, w2h, nw);
    }
    router_kernel<<<(N + 7) / 8, 256>>>(x, Wr, N);
    offsets_kernel<<<1, 32>>>();

    dim3 g1(MAXN / 128, HDIM / 256, EXP);
    moe_gemm<CDIM, HDIM, 0><<<g1, 256, GSMEM>>>(xh, w1h, b1, nullptr);

    dim3 g2(MAXN / 128, CDIM / 256, EXP);
    moe_gemm<HDIM, CDIM, 1><<<g2, 256, GSMEM>>>(hb, w2h, b2, out);

    util_kernel<<<1, 32>>>(out, NC);
}

// round 7
// speedup vs baseline: 7.3357x; 1.0371x over previous
#include <cuda_runtime.h>
#include <cuda_fp16.h>
#include <math.h>

#define CDIM 768
#define EXP 8
#define HDIM 3072
#define MAXN 8192            // 2^13; pack = (e<<13)|slot

// ---- scratch (device globals; no cudaMalloc allowed) ----
__device__ int    d_fill[EXP];
__device__ int    d_off[EXP];
__device__ int    d_tok[EXP * MAXN];
__device__ float  d_wgt[EXP * MAXN];
__device__ int    d_slot[2 * MAXN];                    // per-token packed (e,slot) x2
__device__ __half d_xh[(size_t)MAXN * CDIM];           // x fp16 [N,C]
__device__ __half d_w1h[(size_t)EXP * CDIM * HDIM];    // W1 fp16
__device__ __half d_w2h[(size_t)EXP * HDIM * CDIM];    // W2 fp16
__device__ __half d_hbufh[(size_t)2 * MAXN * HDIM];    // hidden fp16
__device__ __half d_ybuf[(size_t)2 * MAXN * CDIM];     // y+b2 fp16, expert-sorted rows

__device__ __forceinline__ unsigned smem_u32(const void* p) {
    unsigned a;
    asm("{ .reg .u64 t; cvta.to.shared.u64 t, %1; cvt.u32.u64 %0, t; }"
        : "=r"(a) : "l"(p));
    return a;
}

__device__ __forceinline__ void mma_f16(float* c, const unsigned* a, const unsigned* b) {
    asm volatile(
        "mma.sync.aligned.m16n8k16.row.col.f32.f16.f16.f32 "
        "{%0,%1,%2,%3}, {%4,%5,%6,%7}, {%8,%9}, {%0,%1,%2,%3};"
        : "+f"(c[0]), "+f"(c[1]), "+f"(c[2]), "+f"(c[3])
        : "r"(a[0]), "r"(a[1]), "r"(a[2]), "r"(a[3]), "r"(b[0]), "r"(b[1]));
}

__device__ __forceinline__ void ldsm4(unsigned* r, unsigned addr) {
    asm volatile("ldmatrix.sync.aligned.m8n8.x4.shared.b16 {%0,%1,%2,%3}, [%4];"
                 : "=r"(r[0]), "=r"(r[1]), "=r"(r[2]), "=r"(r[3]) : "r"(addr));
}
__device__ __forceinline__ void ldsm4t(unsigned* r, unsigned addr) {
    asm volatile("ldmatrix.sync.aligned.m8n8.x4.trans.shared.b16 {%0,%1,%2,%3}, [%4];"
                 : "=r"(r[0]), "=r"(r[1]), "=r"(r[2]), "=r"(r[3]) : "r"(addr));
}

// ---------------------------------------------------------------------------
__global__ void reset_kernel() {
    if (threadIdx.x < EXP) d_fill[threadIdx.x] = 0;
}

// fp32 -> fp16, 8 elems/thread; n8 = count/8
__global__ void cvt_half_kernel(const float* __restrict__ in, __half* __restrict__ outp,
                                long n8) {
    long i = (long)blockIdx.x * blockDim.x + threadIdx.x;
    if (i < n8) {
        const float4* s = reinterpret_cast<const float4*>(in) + i * 2;
        float4 v0 = s[0], v1 = s[1];
        __half2 h0 = __floats2half2_rn(v0.x, v0.y);
        __half2 h1 = __floats2half2_rn(v0.z, v0.w);
        __half2 h2 = __floats2half2_rn(v1.x, v1.y);
        __half2 h3 = __floats2half2_rn(v1.z, v1.w);
        uint4 o;
        o.x = *reinterpret_cast<unsigned*>(&h0);
        o.y = *reinterpret_cast<unsigned*>(&h1);
        o.z = *reinterpret_cast<unsigned*>(&h2);
        o.w = *reinterpret_cast<unsigned*>(&h3);
        reinterpret_cast<uint4*>(outp)[i] = o;
    }
}

// ---------------------------------------------------------------------------
// router: 1 warp per token; records token lists AND per-token packed slots
// ---------------------------------------------------------------------------
__global__ void router_kernel(const float* __restrict__ x,
                              const float* __restrict__ Wr, int N) {
    int gw   = (blockIdx.x * blockDim.x + threadIdx.x) >> 5;
    int lane = threadIdx.x & 31;
    if (gw >= N) return;
    const float* xr = x + (size_t)gw * CDIM;

    float acc[EXP];
#pragma unroll
    for (int e = 0; e < EXP; e++) acc[e] = 0.0f;
    for (int k = lane; k < CDIM; k += 32) {
        float xv = xr[k];
        const float4* w4 = reinterpret_cast<const float4*>(Wr + (size_t)k * EXP);
        float4 w0 = w4[0], w1 = w4[1];
        acc[0] += xv * w0.x; acc[1] += xv * w0.y;
        acc[2] += xv * w0.z; acc[3] += xv * w0.w;
        acc[4] += xv * w1.x; acc[5] += xv * w1.y;
        acc[6] += xv * w1.z; acc[7] += xv * w1.w;
    }
#pragma unroll
    for (int e = 0; e < EXP; e++)
#pragma unroll
        for (int off = 16; off > 0; off >>= 1)
            acc[e] += __shfl_xor_sync(0xFFFFFFFFu, acc[e], off);

    if (lane == 0) {
        float m = acc[0];
#pragma unroll
        for (int e = 1; e < EXP; e++) m = fmaxf(m, acc[e]);
        float p[EXP], s = 0.0f;
#pragma unroll
        for (int e = 0; e < EXP; e++) { p[e] = expf(acc[e] - m); s += p[e]; }
        float inv = 1.0f / s;
#pragma unroll
        for (int e = 0; e < EXP; e++) p[e] *= inv;
        int i1 = 0;
#pragma unroll
        for (int e = 1; e < EXP; e++) if (p[e] > p[i1]) i1 = e;
        int i2 = (i1 == 0) ? 1 : 0;
#pragma unroll
        for (int e = 0; e < EXP; e++)
            if (e != i1 && p[e] > p[i2]) i2 = e;
        float denom = p[i1] + p[i2] + 1e-9f;
        float w1 = p[i1] / denom, w2 = p[i2] / denom;
        int s1 = atomicAdd(&d_fill[i1], 1);
        int p1 = (i1 << 13) | s1;
        d_tok[p1] = gw; d_wgt[p1] = w1; d_slot[gw] = p1;
        int s2 = atomicAdd(&d_fill[i2], 1);
        int p2 = (i2 << 13) | s2;
        d_tok[p2] = gw; d_wgt[p2] = w2; d_slot[MAXN + gw] = p2;
    }
}

__global__ void offsets_kernel() {
    if (threadIdx.x == 0) {
        int o = 0;
        for (int e = 0; e < EXP; e++) { d_off[e] = o; o += d_fill[e]; }
    }
}

// ---------------------------------------------------------------------------
// fp16 mma.sync GEMM, CTA 128x256, BK=64, 256 thr, 8 warps (2m x 4n),
// warp tile 64x64, ldmatrix, 3-stage cp.async pipeline (1 sync/iter).
// smem: [0:512) tok, [1024) A0 A1 A2 (3x16K) B0 B1 B2 (3x32K) = 148480 B
// MODE 0: A = gathered x rows -> gelu -> hbuf
// MODE 1: A = hbuf rows -> (y + b2) fp16 -> ybuf (plain stores)
// ---------------------------------------------------------------------------
#define GSMEM 148480

template<int KD, int ND, int MODE>
__global__ void __launch_bounds__(256)
moe_gemm(const __half* __restrict__ Amat, const __half* __restrict__ Bmat,
         const float* __restrict__ bias) {
    constexpr int ITERS = KD / 64;

    extern __shared__ char smem[];
    int* stok = reinterpret_cast<int*>(smem);
    const unsigned sA = smem_u32(smem + 1024);          // 3 x 16384
    const unsigned sB = sA + 49152;                     // 3 x 32768

    const int e   = blockIdx.z;
    const int cnt = d_fill[e];
    const int m0  = blockIdx.x * 128;
    if (m0 >= cnt) return;
    const int j0  = blockIdx.y * 256;
    const int off = d_off[e];
    const int tid = threadIdx.x;
    const int lane = tid & 31, w = tid >> 5;
    const int wm = (w & 1) * 64, wn = (w >> 1) * 64;

    if (MODE == 0 && tid < 128) {
        int gm = m0 + tid;
        stok[tid] = (gm < cnt) ? d_tok[(e << 13) | gm] : -1;
    }
    __syncthreads();

    // ---- cp.async slots: A 4 chunks (16B), B 8 chunks per thread ----
    const __half* agp[4]; unsigned aso[4], asz[4];
#pragma unroll
    for (int t = 0; t < 4; t++) {
        int idx = tid + t * 256, row = idx >> 3, c = idx & 7;
        bool ok; size_t base;
        if (MODE == 0) { int tk = stok[row]; ok = (tk >= 0); base = ok ? (size_t)tk * KD : 0; }
        else           { int gm = m0 + row;  ok = (gm < cnt); base = ok ? (size_t)(off + gm) * KD : 0; }
        agp[t] = Amat + base + c * 8;
        asz[t] = ok ? 16u : 0u;
        aso[t] = row * 128 + ((c ^ (row & 7)) * 16);
    }
    const __half* bbase = Bmat + (size_t)e * CDIM * HDIM + j0;
    int bgo[8]; unsigned bso[8];
#pragma unroll
    for (int t = 0; t < 8; t++) {
        int idx = tid + t * 256, row = idx >> 5, c = idx & 31;
        bgo[t] = row * ND + c * 8;
        bso[t] = row * 512 + ((c ^ (row & 7)) * 16);
    }

    auto load_tile = [&](int p, int k0) {
        unsigned Ab = sA + p * 16384, Bb = sB + p * 32768;
#pragma unroll
        for (int t = 0; t < 4; t++)
            asm volatile("cp.async.cg.shared.global [%0], [%1], 16, %2;"
                         :: "r"(Ab + aso[t]), "l"(agp[t] + k0), "r"(asz[t]) : "memory");
        const __half* bsrc = bbase + (size_t)k0 * ND;
#pragma unroll
        for (int t = 0; t < 8; t++)
            asm volatile("cp.async.cg.shared.global [%0], [%1], 16;"
                         :: "r"(Bb + bso[t]), "l"(bsrc + bgo[t]) : "memory");
    };

    float acc[4][8][4];
#pragma unroll
    for (int mt = 0; mt < 4; mt++)
#pragma unroll
        for (int nt = 0; nt < 8; nt++)
#pragma unroll
            for (int i = 0; i < 4; i++) acc[mt][nt][i] = 0.0f;

    const int rsel = (lane & 7) | (lane & 8);
    const int kh   = (lane >> 4) & 1;
    const int l7   = lane & 7;

    // prologue: stages 0,1 (one commit group each)
    load_tile(0, 0);
    asm volatile("cp.async.commit_group;" ::: "memory");
    load_tile(1, 64);
    asm volatile("cp.async.commit_group;" ::: "memory");

    for (int i = 0; i < ITERS; i++) {
        const int p = i % 3;
        asm volatile("cp.async.wait_group 1;" ::: "memory");
        __syncthreads();
        // load stage i+2 into buf (i+2)%3 (= stage i-1's buf; its compute done by all)
        if (i + 2 < ITERS) load_tile((i + 2) % 3, (i + 2) * 64);
        asm volatile("cp.async.commit_group;" ::: "memory");

        const unsigned Ab = sA + p * 16384, Bb = sB + p * 32768;
#pragma unroll
        for (int ks = 0; ks < 4; ks++) {
            unsigned afr[4][4];
#pragma unroll
            for (int mt = 0; mt < 4; mt++) {
                unsigned ad = Ab + (wm + mt * 16 + rsel) * 128
                            + (((ks * 2 + kh) ^ l7) * 16);
                ldsm4(afr[mt], ad);
            }
            unsigned bfr[8][2];
#pragma unroll
            for (int bt = 0; bt < 4; bt++) {
                int krow = ks * 16 + rsel;
                unsigned bd = Bb + krow * 512
                            + ((((wn >> 3) + bt * 2 + kh) ^ l7) * 16);
                unsigned r[4];
                ldsm4t(r, bd);
                bfr[bt * 2][0] = r[0];     bfr[bt * 2][1] = r[1];
                bfr[bt * 2 + 1][0] = r[2]; bfr[bt * 2 + 1][1] = r[3];
            }
#pragma unroll
            for (int mt = 0; mt < 4; mt++)
#pragma unroll
                for (int nt = 0; nt < 8; nt++)
                    mma_f16(acc[mt][nt], afr[mt], bfr[nt]);
        }
    }

    // ---- epilogue: fp16 stores (no atomics) ----
#pragma unroll
    for (int mt = 0; mt < 4; mt++) {
#pragma unroll
        for (int half = 0; half < 2; half++) {
            int lrow = wm + mt * 16 + (lane >> 2) + half * 8;
            int gm   = m0 + lrow;
            if (gm >= cnt) continue;
            __half* hrow = (MODE == 0)
                ? (d_hbufh + (size_t)(off + gm) * HDIM)
                : (d_ybuf  + (size_t)(off + gm) * CDIM);
#pragma unroll
            for (int nt = 0; nt < 8; nt++) {
                int col = j0 + wn + nt * 8 + (lane & 3) * 2;
                float v0 = acc[mt][nt][half * 2 + 0] + bias[(size_t)e * ND + col];
                float v1 = acc[mt][nt][half * 2 + 1] + bias[(size_t)e * ND + col + 1];
                if (MODE == 0) {
                    v0 = 0.5f * v0 * (1.0f + erff(v0 * 0.70710678118654752f));
                    v1 = 0.5f * v1 * (1.0f + erff(v1 * 0.70710678118654752f));
                }
                *reinterpret_cast<__half2*>(hrow + col) = __floats2half2_rn(v0, v1);
            }
        }
    }
}

// ---------------------------------------------------------------------------
// combine: out[tok] = w1*ybuf[row1] + w2*ybuf[row2]   (4 cols / thread)
// ---------------------------------------------------------------------------
__global__ void combine_kernel(float* __restrict__ out, int N) {
    int gid  = blockIdx.x * blockDim.x + threadIdx.x;
    int col4 = gid * 4;
    int tok  = col4 / CDIM;
    int c    = col4 % CDIM;
    if (tok >= N) return;

    int p1 = d_slot[tok], p2 = d_slot[MAXN + tok];
    int r1 = d_off[p1 >> 13] + (p1 & (MAXN - 1));
    int r2 = d_off[p2 >> 13] + (p2 & (MAXN - 1));
    float w1 = d_wgt[p1], w2 = d_wgt[p2];

    const __half2* a = reinterpret_cast<const __half2*>(d_ybuf + (size_t)r1 * CDIM + c);
    const __half2* b = reinterpret_cast<const __half2*>(d_ybuf + (size_t)r2 * CDIM + c);
    float2 a0 = __half22float2(a[0]), a1 = __half22float2(a[1]);
    float2 b0 = __half22float2(b[0]), b1 = __half22float2(b[1]);
    float4 o;
    o.x = w1 * a0.x + w2 * b0.x;
    o.y = w1 * a0.y + w2 * b0.y;
    o.z = w1 * a1.x + w2 * b1.x;
    o.w = w1 * a1.y + w2 * b1.y;
    *reinterpret_cast<float4*>(out + (size_t)tok * CDIM + c) = o;
}

// ---------------------------------------------------------------------------
__global__ void util_kernel(float* __restrict__ out, int NC) {
    int e = threadIdx.x;
    if (e < EXP) {
        float tot = 0.0f;
        for (int j = 0; j < EXP; j++) tot += (float)d_fill[j];
        out[NC + e] = (float)d_fill[e] / (tot + 1e-9f);
    }
}

// ---------------------------------------------------------------------------
extern "C" void kernel_launch(void* const* d_in, const int* in_sizes, int n_in,
                              void* d_out, int out_size) {
    const float* x  = (const float*)d_in[0];
    const float* Wr = (const float*)d_in[1];
    const float* W1 = (const float*)d_in[2];
    const float* b1 = (const float*)d_in[3];
    const float* W2 = (const float*)d_in[4];
    const float* b2 = (const float*)d_in[5];
    float* out = (float*)d_out;

    int N  = in_sizes[0] / CDIM;   // 8192
    int NC = N * CDIM;

    static int init_done = 0;
    if (!init_done) {
        cudaFuncSetAttribute(moe_gemm<CDIM, HDIM, 0>,
                             cudaFuncAttributeMaxDynamicSharedMemorySize, GSMEM);
        cudaFuncSetAttribute(moe_gemm<HDIM, CDIM, 1>,
                             cudaFuncAttributeMaxDynamicSharedMemorySize, GSMEM);
        init_done = 1;
    }

    __half *xh, *w1h, *w2h;
    cudaGetSymbolAddress((void**)&xh,  d_xh);
    cudaGetSymbolAddress((void**)&w1h, d_w1h);
    cudaGetSymbolAddress((void**)&w2h, d_w2h);

    reset_kernel<<<1, 32>>>();
    cvt_half_kernel<<<(NC / 8 + 255) / 256, 256>>>(x, xh, NC / 8);
    {
        long nw = (long)EXP * CDIM * HDIM / 8;
        cvt_half_kernel<<<(int)((nw + 255) / 256), 256>>>(W1, w1h, nw);
        cvt_half_kernel<<<(int)((nw + 255) / 256), 256>>>(W2, w2h, nw);
    }
    router_kernel<<<(N + 7) / 8, 256>>>(x, Wr, N);
    offsets_kernel<<<1, 32>>>();

    dim3 g1(MAXN / 128, HDIM / 256, EXP);
    moe_gemm<CDIM, HDIM, 0><<<g1, 256, GSMEM>>>(xh, w1h, b1);

    __half* hb; cudaGetSymbolAddress((void**)&hb, d_hbufh);
    dim3 g2(MAXN / 128, CDIM / 256, EXP);
    moe_gemm<HDIM, CDIM, 1><<<g2, 256, GSMEM>>>(hb, w2h, b2);

    combine_kernel<<<(NC / 4 + 255) / 256, 256>>>(out, N);
    util_kernel<<<1, 32>>>(out, NC);
}

// round 10
// speedup vs baseline: 8.1651x; 1.1131x over previous
#include <cuda_runtime.h>
#include <cuda_fp16.h>
#include <math.h>

#define CDIM 768
#define EXP 8
#define HDIM 3072
#define MAXN 8192            // 2^13; pack = (e<<13)|slot

// ---- scratch (device globals; no cudaMalloc allowed) ----
__device__ int    d_fill[EXP];
__device__ int    d_off[EXP];
__device__ int    d_tok[EXP * MAXN];
__device__ float  d_wgt[EXP * MAXN];
__device__ int    d_slot[2 * MAXN];
__device__ __half d_xh[(size_t)MAXN * CDIM];
__device__ __half d_w1h[(size_t)EXP * CDIM * HDIM];
__device__ __half d_w2h[(size_t)EXP * HDIM * CDIM];
__device__ __half d_hbufh[(size_t)2 * MAXN * HDIM];
__device__ __half d_ybuf[(size_t)2 * MAXN * CDIM];

__device__ __forceinline__ unsigned smem_u32(const void* p) {
    unsigned a;
    asm("{ .reg .u64 t; cvta.to.shared.u64 t, %1; cvt.u32.u64 %0, t; }"
        : "=r"(a) : "l"(p));
    return a;
}

__device__ __forceinline__ void mma_f16(float* c, const unsigned* a, const unsigned* b) {
    asm volatile(
        "mma.sync.aligned.m16n8k16.row.col.f32.f16.f16.f32 "
        "{%0,%1,%2,%3}, {%4,%5,%6,%7}, {%8,%9}, {%0,%1,%2,%3};"
        : "+f"(c[0]), "+f"(c[1]), "+f"(c[2]), "+f"(c[3])
        : "r"(a[0]), "r"(a[1]), "r"(a[2]), "r"(a[3]), "r"(b[0]), "r"(b[1]));
}

__device__ __forceinline__ void ldsm4(unsigned* r, unsigned addr) {
    asm volatile("ldmatrix.sync.aligned.m8n8.x4.shared.b16 {%0,%1,%2,%3}, [%4];"
                 : "=r"(r[0]), "=r"(r[1]), "=r"(r[2]), "=r"(r[3]) : "r"(addr));
}
__device__ __forceinline__ void ldsm4t(unsigned* r, unsigned addr) {
    asm volatile("ldmatrix.sync.aligned.m8n8.x4.trans.shared.b16 {%0,%1,%2,%3}, [%4];"
                 : "=r"(r[0]), "=r"(r[1]), "=r"(r[2]), "=r"(r[3]) : "r"(addr));
}

// ---------------------------------------------------------------------------
__global__ void reset_kernel() {
    if (threadIdx.x < EXP) d_fill[threadIdx.x] = 0;
}

// fp32 -> fp16, 8 elems/thread
__global__ void cvt_half_kernel(const float* __restrict__ in, __half* __restrict__ outp,
                                long n8) {
    long i = (long)blockIdx.x * blockDim.x + threadIdx.x;
    if (i < n8) {
        const float4* s = reinterpret_cast<const float4*>(in) + i * 2;
        float4 v0 = s[0], v1 = s[1];
        __half2 h0 = __floats2half2_rn(v0.x, v0.y);
        __half2 h1 = __floats2half2_rn(v0.z, v0.w);
        __half2 h2 = __floats2half2_rn(v1.x, v1.y);
        __half2 h3 = __floats2half2_rn(v1.z, v1.w);
        uint4 o;
        o.x = *reinterpret_cast<unsigned*>(&h0);
        o.y = *reinterpret_cast<unsigned*>(&h1);
        o.z = *reinterpret_cast<unsigned*>(&h2);
        o.w = *reinterpret_cast<unsigned*>(&h3);
        reinterpret_cast<uint4*>(outp)[i] = o;
    }
}

// ---------------------------------------------------------------------------
// router: 1 warp per token
// ---------------------------------------------------------------------------
__global__ void router_kernel(const float* __restrict__ x,
                              const float* __restrict__ Wr, int N) {
    int gw   = (blockIdx.x * blockDim.x + threadIdx.x) >> 5;
    int lane = threadIdx.x & 31;
    if (gw >= N) return;
    const float* xr = x + (size_t)gw * CDIM;

    float acc[EXP];
#pragma unroll
    for (int e = 0; e < EXP; e++) acc[e] = 0.0f;
    for (int k = lane; k < CDIM; k += 32) {
        float xv = xr[k];
        const float4* w4 = reinterpret_cast<const float4*>(Wr + (size_t)k * EXP);
        float4 w0 = w4[0], w1 = w4[1];
        acc[0] += xv * w0.x; acc[1] += xv * w0.y;
        acc[2] += xv * w0.z; acc[3] += xv * w0.w;
        acc[4] += xv * w1.x; acc[5] += xv * w1.y;
        acc[6] += xv * w1.z; acc[7] += xv * w1.w;
    }
#pragma unroll
    for (int e = 0; e < EXP; e++)
#pragma unroll
        for (int off = 16; off > 0; off >>= 1)
            acc[e] += __shfl_xor_sync(0xFFFFFFFFu, acc[e], off);

    if (lane == 0) {
        float m = acc[0];
#pragma unroll
        for (int e = 1; e < EXP; e++) m = fmaxf(m, acc[e]);
        float p[EXP], s = 0.0f;
#pragma unroll
        for (int e = 0; e < EXP; e++) { p[e] = expf(acc[e] - m); s += p[e]; }
        float inv = 1.0f / s;
#pragma unroll
        for (int e = 0; e < EXP; e++) p[e] *= inv;
        int i1 = 0;
#pragma unroll
        for (int e = 1; e < EXP; e++) if (p[e] > p[i1]) i1 = e;
        int i2 = (i1 == 0) ? 1 : 0;
#pragma unroll
        for (int e = 0; e < EXP; e++)
            if (e != i1 && p[e] > p[i2]) i2 = e;
        float denom = p[i1] + p[i2] + 1e-9f;
        float w1 = p[i1] / denom, w2 = p[i2] / denom;
        int s1 = atomicAdd(&d_fill[i1], 1);
        int p1 = (i1 << 13) | s1;
        d_tok[p1] = gw; d_wgt[p1] = w1; d_slot[gw] = p1;
        int s2 = atomicAdd(&d_fill[i2], 1);
        int p2 = (i2 << 13) | s2;
        d_tok[p2] = gw; d_wgt[p2] = w2; d_slot[MAXN + gw] = p2;
    }
}

__global__ void offsets_kernel() {
    if (threadIdx.x == 0) {
        int o = 0;
        for (int e = 0; e < EXP; e++) { d_off[e] = o; o += d_fill[e]; }
    }
}

// ---------------------------------------------------------------------------
// fp16 mma.sync GEMM, CTA 128x256, BK=64, 512 thr, 16 warps (2m x 8n),
// warp tile 64x32, ldmatrix, 3-stage cp.async, one sync per iter.
// smem: [0:512) tok, [1024) A0..A2 (3x16K) B0..B2 (3x32K) = 148480 B
// ---------------------------------------------------------------------------
#define GSMEM 148480

template<int KD, int ND, int MODE>
__global__ void __launch_bounds__(512, 1)
moe_gemm(const __half* __restrict__ Amat, const __half* __restrict__ Bmat,
         const float* __restrict__ bias) {
    constexpr int ITERS = KD / 64;

    extern __shared__ char smem[];
    int* stok = reinterpret_cast<int*>(smem);
    const unsigned sA = smem_u32(smem + 1024);          // 3 x 16384
    const unsigned sB = sA + 49152;                     // 3 x 32768

    const int e   = blockIdx.z;
    const int cnt = d_fill[e];
    const int m0  = blockIdx.x * 128;
    if (m0 >= cnt) return;
    const int j0  = blockIdx.y * 256;
    const int off = d_off[e];
    const int tid = threadIdx.x;
    const int lane = tid & 31, w = tid >> 5;
    const int wm = (w & 1) * 64, wn = (w >> 1) * 32;

    if (MODE == 0 && tid < 128) {
        int gm = m0 + tid;
        stok[tid] = (gm < cnt) ? d_tok[(e << 13) | gm] : -1;
    }
    __syncthreads();

    // ---- cp.async slots: A 2 chunks, B 4 chunks per thread (16B each) ----
    const __half* agp[2]; unsigned aso[2], asz[2];
#pragma unroll
    for (int t = 0; t < 2; t++) {
        int idx = tid + t * 512, row = idx >> 3, c = idx & 7;
        bool ok; size_t base;
        if (MODE == 0) { int tk = stok[row]; ok = (tk >= 0); base = ok ? (size_t)tk * KD : 0; }
        else           { int gm = m0 + row;  ok = (gm < cnt); base = ok ? (size_t)(off + gm) * KD : 0; }
        agp[t] = Amat + base + c * 8;
        asz[t] = ok ? 16u : 0u;
        aso[t] = row * 128 + ((c ^ (row & 7)) * 16);
    }
    const __half* bbase = Bmat + (size_t)e * CDIM * HDIM + j0;
    int bgo[4]; unsigned bso[4];
#pragma unroll
    for (int t = 0; t < 4; t++) {
        int idx = tid + t * 512, row = idx >> 5, c = idx & 31;
        bgo[t] = row * ND + c * 8;
        bso[t] = row * 512 + ((c ^ (row & 7)) * 16);
    }

    auto load_tile = [&](int p, int k0) {
        unsigned Ab = sA + p * 16384, Bb = sB + p * 32768;
#pragma unroll
        for (int t = 0; t < 2; t++)
            asm volatile("cp.async.cg.shared.global [%0], [%1], 16, %2;"
                         :: "r"(Ab + aso[t]), "l"(agp[t] + k0), "r"(asz[t]) : "memory");
        const __half* bsrc = bbase + (size_t)k0 * ND;
#pragma unroll
        for (int t = 0; t < 4; t++)
            asm volatile("cp.async.cg.shared.global [%0], [%1], 16;"
                         :: "r"(Bb + bso[t]), "l"(bsrc + bgo[t]) : "memory");
    };

    float acc[4][4][4];
#pragma unroll
    for (int mt = 0; mt < 4; mt++)
#pragma unroll
        for (int nt = 0; nt < 4; nt++)
#pragma unroll
            for (int i = 0; i < 4; i++) acc[mt][nt][i] = 0.0f;

    const int rsel = (lane & 7) | (lane & 8);
    const int kh   = (lane >> 4) & 1;
    const int l7   = lane & 7;

    load_tile(0, 0);
    asm volatile("cp.async.commit_group;" ::: "memory");
    load_tile(1, 64);
    asm volatile("cp.async.commit_group;" ::: "memory");

    for (int i = 0; i < ITERS; i++) {
        const int p = i % 3;
        asm volatile("cp.async.wait_group 1;" ::: "memory");
        __syncthreads();
        if (i + 2 < ITERS) load_tile((i + 2) % 3, (i + 2) * 64);
        asm volatile("cp.async.commit_group;" ::: "memory");

        const unsigned Ab = sA + p * 16384, Bb = sB + p * 32768;
#pragma unroll
        for (int ks = 0; ks < 4; ks++) {
            unsigned afr[4][4];
#pragma unroll
            for (int mt = 0; mt < 4; mt++) {
                unsigned ad = Ab + (wm + mt * 16 + rsel) * 128
                            + (((ks * 2 + kh) ^ l7) * 16);
                ldsm4(afr[mt], ad);
            }
            unsigned bfr[4][2];
#pragma unroll
            for (int bt = 0; bt < 2; bt++) {
                int krow = ks * 16 + rsel;
                unsigned bd = Bb + krow * 512
                            + ((((wn >> 3) + bt * 2 + kh) ^ l7) * 16);
                unsigned r[4];
                ldsm4t(r, bd);
                bfr[bt * 2][0] = r[0];     bfr[bt * 2][1] = r[1];
                bfr[bt * 2 + 1][0] = r[2]; bfr[bt * 2 + 1][1] = r[3];
            }
#pragma unroll
            for (int mt = 0; mt < 4; mt++)
#pragma unroll
                for (int nt = 0; nt < 4; nt++)
                    mma_f16(acc[mt][nt], afr[mt], bfr[nt]);
        }
    }

    // ---- epilogue ----
#pragma unroll
    for (int mt = 0; mt < 4; mt++) {
#pragma unroll
        for (int half = 0; half < 2; half++) {
            int lrow = wm + mt * 16 + (lane >> 2) + half * 8;
            int gm   = m0 + lrow;
            if (gm >= cnt) continue;
            __half* hrow = (MODE == 0)
                ? (d_hbufh + (size_t)(off + gm) * HDIM)
                : (d_ybuf  + (size_t)(off + gm) * CDIM);
#pragma unroll
            for (int nt = 0; nt < 4; nt++) {
                int col = j0 + wn + nt * 8 + (lane & 3) * 2;
                float v0 = acc[mt][nt][half * 2 + 0] + bias[(size_t)e * ND + col];
                float v1 = acc[mt][nt][half * 2 + 1] + bias[(size_t)e * ND + col + 1];
                if (MODE == 0) {
                    v0 = 0.5f * v0 * (1.0f + erff(v0 * 0.70710678118654752f));
                    v1 = 0.5f * v1 * (1.0f + erff(v1 * 0.70710678118654752f));
                }
                *reinterpret_cast<__half2*>(hrow + col) = __floats2half2_rn(v0, v1);
            }
        }
    }
}

// ---------------------------------------------------------------------------
// combine: out[tok] = w1*ybuf[row1] + w2*ybuf[row2]
// ---------------------------------------------------------------------------
__global__ void combine_kernel(float* __restrict__ out, int N) {
    int gid  = blockIdx.x * blockDim.x + threadIdx.x;
    int col4 = gid * 4;
    int tok  = col4 / CDIM;
    int c    = col4 % CDIM;
    if (tok >= N) return;

    int p1 = d_slot[tok], p2 = d_slot[MAXN + tok];
    int r1 = d_off[p1 >> 13] + (p1 & (MAXN - 1));
    int r2 = d_off[p2 >> 13] + (p2 & (MAXN - 1));
    float w1 = d_wgt[p1], w2 = d_wgt[p2];

    const __half2* a = reinterpret_cast<const __half2*>(d_ybuf + (size_t)r1 * CDIM + c);
    const __half2* b = reinterpret_cast<const __half2*>(d_ybuf + (size_t)r2 * CDIM + c);
    float2 a0 = __half22float2(a[0]), a1 = __half22float2(a[1]);
    float2 b0 = __half22float2(b[0]), b1 = __half22float2(b[1]);
    float4 o;
    o.x = w1 * a0.x + w2 * b0.x;
    o.y = w1 * a0.y + w2 * b0.y;
    o.z = w1 * a1.x + w2 * b1.x;
    o.w = w1 * a1.y + w2 * b1.y;
    *reinterpret_cast<float4*>(out + (size_t)tok * CDIM + c) = o;
}

// ---------------------------------------------------------------------------
__global__ void util_kernel(float* __restrict__ out, int NC) {
    int e = threadIdx.x;
    if (e < EXP) {
        float tot = 0.0f;
        for (int j = 0; j < EXP; j++) tot += (float)d_fill[j];
        out[NC + e] = (float)d_fill[e] / (tot + 1e-9f);
    }
}

// ---------------------------------------------------------------------------
extern "C" void kernel_launch(void* const* d_in, const int* in_sizes, int n_in,
                              void* d_out, int out_size) {
    const float* x  = (const float*)d_in[0];
    const float* Wr = (const float*)d_in[1];
    const float* W1 = (const float*)d_in[2];
    const float* b1 = (const float*)d_in[3];
    const float* W2 = (const float*)d_in[4];
    const float* b2 = (const float*)d_in[5];
    float* out = (float*)d_out;

    int N  = in_sizes[0] / CDIM;   // 8192
    int NC = N * CDIM;

    static cudaStream_t s1 = nullptr, s2 = nullptr;
    static cudaEvent_t evRoot, evW1, evW2;
    static int init_done = 0;
    if (!init_done) {
        cudaFuncSetAttribute(moe_gemm<CDIM, HDIM, 0>,
                             cudaFuncAttributeMaxDynamicSharedMemorySize, GSMEM);
        cudaFuncSetAttribute(moe_gemm<HDIM, CDIM, 1>,
                             cudaFuncAttributeMaxDynamicSharedMemorySize, GSMEM);
        cudaStreamCreateWithFlags(&s1, cudaStreamNonBlocking);
        cudaStreamCreateWithFlags(&s2, cudaStreamNonBlocking);
        cudaEventCreateWithFlags(&evRoot, cudaEventDisableTiming);
        cudaEventCreateWithFlags(&evW1, cudaEventDisableTiming);
        cudaEventCreateWithFlags(&evW2, cudaEventDisableTiming);
        init_done = 1;
    }

    __half *xh, *w1h, *w2h;
    cudaGetSymbolAddress((void**)&xh,  d_xh);
    cudaGetSymbolAddress((void**)&w1h, d_w1h);
    cudaGetSymbolAddress((void**)&w2h, d_w2h);

    // ---- fork: converts on s1/s2, routing on main ----
    cudaEventRecord(evRoot, 0);
    cudaStreamWaitEvent(s1, evRoot, 0);
    cudaStreamWaitEvent(s2, evRoot, 0);

    reset_kernel<<<1, 32>>>();
    router_kernel<<<(N + 7) / 8, 256>>>(x, Wr, N);
    offsets_kernel<<<1, 32>>>();

    cvt_half_kernel<<<(NC / 8 + 255) / 256, 256, 0, s1>>>(x, xh, NC / 8);
    {
        long nw = (long)EXP * CDIM * HDIM / 8;
        cvt_half_kernel<<<(int)((nw + 255) / 256), 256, 0, s1>>>(W1, w1h, nw);
        cvt_half_kernel<<<(int)((nw + 255) / 256), 256, 0, s2>>>(W2, w2h, nw);
    }
    cudaEventRecord(evW1, s1);
    cudaEventRecord(evW2, s2);

    // ---- join for gemm1 (needs xh, w1h, routing) ----
    cudaStreamWaitEvent(0, evW1, 0);
    dim3 g1(MAXN / 128, HDIM / 256, EXP);
    moe_gemm<CDIM, HDIM, 0><<<g1, 512, GSMEM>>>(xh, w1h, b1);

    // ---- join for gemm2 (needs w2h) ----
    cudaStreamWaitEvent(0, evW2, 0);
    __half* hb; cudaGetSymbolAddress((void**)&hb, d_hbufh);
    dim3 g2(MAXN / 128, CDIM / 256, EXP);
    moe_gemm<HDIM, CDIM, 1><<<g2, 512, GSMEM>>>(hb, w2h, b2);

    combine_kernel<<<(NC / 4 + 255) / 256, 256>>>(out, N);
    util_kernel<<<1, 32>>>(out, NC);
}

// round 11
// speedup vs baseline: 8.1997x; 1.0042x over previous
#include <cuda_runtime.h>
#include <cuda_fp16.h>
#include <math.h>

#define CDIM 768
#define EXP 8
#define HDIM 3072
#define MAXN 8192            // 2^13; pack = (e<<13)|slot

// ---- scratch (device globals; no cudaMalloc allowed) ----
__device__ int    d_fill[EXP];
__device__ int    d_off[EXP];
__device__ int    d_tok[EXP * MAXN];
__device__ float  d_wgt[EXP * MAXN];
__device__ int    d_slot[2 * MAXN];
__device__ int    d_tl[EXP * (MAXN / 128)];   // tile list: (e<<16)|mblock
__device__ int    d_ntl;                      // number of (e,mb) pairs
__device__ int    d_wq[2];                    // work counters (per GEMM)
__device__ __half d_xh[(size_t)MAXN * CDIM];
__device__ __half d_w1h[(size_t)EXP * CDIM * HDIM];
__device__ __half d_w2h[(size_t)EXP * HDIM * CDIM];
__device__ __half d_hbufh[(size_t)2 * MAXN * HDIM];
__device__ __half d_ybuf[(size_t)2 * MAXN * CDIM];

__device__ __forceinline__ unsigned smem_u32(const void* p) {
    unsigned a;
    asm("{ .reg .u64 t; cvta.to.shared.u64 t, %1; cvt.u32.u64 %0, t; }"
        : "=r"(a) : "l"(p));
    return a;
}

__device__ __forceinline__ void mma_f16(float* c, const unsigned* a, const unsigned* b) {
    asm volatile(
        "mma.sync.aligned.m16n8k16.row.col.f32.f16.f16.f32 "
        "{%0,%1,%2,%3}, {%4,%5,%6,%7}, {%8,%9}, {%0,%1,%2,%3};"
        : "+f"(c[0]), "+f"(c[1]), "+f"(c[2]), "+f"(c[3])
        : "r"(a[0]), "r"(a[1]), "r"(a[2]), "r"(a[3]), "r"(b[0]), "r"(b[1]));
}

__device__ __forceinline__ void ldsm4(unsigned* r, unsigned addr) {
    asm volatile("ldmatrix.sync.aligned.m8n8.x4.shared.b16 {%0,%1,%2,%3}, [%4];"
                 : "=r"(r[0]), "=r"(r[1]), "=r"(r[2]), "=r"(r[3]) : "r"(addr));
}
__device__ __forceinline__ void ldsm4t(unsigned* r, unsigned addr) {
    asm volatile("ldmatrix.sync.aligned.m8n8.x4.trans.shared.b16 {%0,%1,%2,%3}, [%4];"
                 : "=r"(r[0]), "=r"(r[1]), "=r"(r[2]), "=r"(r[3]) : "r"(addr));
}

// ---------------------------------------------------------------------------
__global__ void reset_kernel() {
    if (threadIdx.x < EXP) d_fill[threadIdx.x] = 0;
}

// fp32 -> fp16, 8 elems/thread
__global__ void cvt_half_kernel(const float* __restrict__ in, __half* __restrict__ outp,
                                long n8) {
    long i = (long)blockIdx.x * blockDim.x + threadIdx.x;
    if (i < n8) {
        const float4* s = reinterpret_cast<const float4*>(in) + i * 2;
        float4 v0 = s[0], v1 = s[1];
        __half2 h0 = __floats2half2_rn(v0.x, v0.y);
        __half2 h1 = __floats2half2_rn(v0.z, v0.w);
        __half2 h2 = __floats2half2_rn(v1.x, v1.y);
        __half2 h3 = __floats2half2_rn(v1.z, v1.w);
        uint4 o;
        o.x = *reinterpret_cast<unsigned*>(&h0);
        o.y = *reinterpret_cast<unsigned*>(&h1);
        o.z = *reinterpret_cast<unsigned*>(&h2);
        o.w = *reinterpret_cast<unsigned*>(&h3);
        reinterpret_cast<uint4*>(outp)[i] = o;
    }
}

// ---------------------------------------------------------------------------
// router: 1 warp per token
// ---------------------------------------------------------------------------
__global__ void router_kernel(const float* __restrict__ x,
                              const float* __restrict__ Wr, int N) {
    int gw   = (blockIdx.x * blockDim.x + threadIdx.x) >> 5;
    int lane = threadIdx.x & 31;
    if (gw >= N) return;
    const float* xr = x + (size_t)gw * CDIM;

    float acc[EXP];
#pragma unroll
    for (int e = 0; e < EXP; e++) acc[e] = 0.0f;
    for (int k = lane; k < CDIM; k += 32) {
        float xv = xr[k];
        const float4* w4 = reinterpret_cast<const float4*>(Wr + (size_t)k * EXP);
        float4 w0 = w4[0], w1 = w4[1];
        acc[0] += xv * w0.x; acc[1] += xv * w0.y;
        acc[2] += xv * w0.z; acc[3] += xv * w0.w;
        acc[4] += xv * w1.x; acc[5] += xv * w1.y;
        acc[6] += xv * w1.z; acc[7] += xv * w1.w;
    }
#pragma unroll
    for (int e = 0; e < EXP; e++)
#pragma unroll
        for (int off = 16; off > 0; off >>= 1)
            acc[e] += __shfl_xor_sync(0xFFFFFFFFu, acc[e], off);

    if (lane == 0) {
        float m = acc[0];
#pragma unroll
        for (int e = 1; e < EXP; e++) m = fmaxf(m, acc[e]);
        float p[EXP], s = 0.0f;
#pragma unroll
        for (int e = 0; e < EXP; e++) { p[e] = expf(acc[e] - m); s += p[e]; }
        float inv = 1.0f / s;
#pragma unroll
        for (int e = 0; e < EXP; e++) p[e] *= inv;
        int i1 = 0;
#pragma unroll
        for (int e = 1; e < EXP; e++) if (p[e] > p[i1]) i1 = e;
        int i2 = (i1 == 0) ? 1 : 0;
#pragma unroll
        for (int e = 0; e < EXP; e++)
            if (e != i1 && p[e] > p[i2]) i2 = e;
        float denom = p[i1] + p[i2] + 1e-9f;
        float w1 = p[i1] / denom, w2 = p[i2] / denom;
        int s1 = atomicAdd(&d_fill[i1], 1);
        int p1 = (i1 << 13) | s1;
        d_tok[p1] = gw; d_wgt[p1] = w1; d_slot[gw] = p1;
        int s2 = atomicAdd(&d_fill[i2], 1);
        int p2 = (i2 << 13) | s2;
        d_tok[p2] = gw; d_wgt[p2] = w2; d_slot[MAXN + gw] = p2;
    }
}

// offsets + tile list + work-counter reset
__global__ void offsets_kernel() {
    if (threadIdx.x == 0) {
        int o = 0, m = 0;
        for (int e = 0; e < EXP; e++) {
            d_off[e] = o;
            int c = d_fill[e];
            o += c;
            int nb = (c + 127) / 128;
            for (int mb = 0; mb < nb; mb++) d_tl[m++] = (e << 16) | mb;
        }
        d_ntl = m;
        d_wq[0] = 0;
        d_wq[1] = 0;
    }
}

// ---------------------------------------------------------------------------
// Persistent fp16 mma.sync GEMM. CTA 128x256, BK=64, 512 thr, 16 warps
// (2m x 8n, warp 64x32), ldmatrix, 3-stage cp.async, 1 sync/iter.
// Tiles pulled from d_wq[MODE] over d_tl x NJ n-blocks (work stealing).
// smem: [0:512) tok, [768) s_t, [1024) A0..A2 (3x16K) B0..B2 (3x32K)
// MODE 0: A = gathered x rows -> gelu -> hbuf
// MODE 1: A = hbuf rows -> (y + b2) fp16 -> ybuf
// ---------------------------------------------------------------------------
#define GSMEM 148480
#define NSM 152

template<int KD, int ND, int MODE>
__global__ void __launch_bounds__(512, 1)
moe_gemm(const __half* __restrict__ Amat, const __half* __restrict__ Bmat,
         const float* __restrict__ bias) {
    constexpr int ITERS = KD / 64;
    constexpr int NJ    = ND / 256;

    extern __shared__ char smem[];
    int* stok = reinterpret_cast<int*>(smem);
    int* s_t  = reinterpret_cast<int*>(smem + 768);
    const unsigned sA = smem_u32(smem + 1024);          // 3 x 16384
    const unsigned sB = sA + 49152;                     // 3 x 32768

    const int tid = threadIdx.x;
    const int lane = tid & 31, w = tid >> 5;
    const int wm = (w & 1) * 64, wn = (w >> 1) * 32;
    const int rsel = (lane & 7) | (lane & 8);
    const int kh   = (lane >> 4) & 1;
    const int l7   = lane & 7;

    const int NT = d_ntl * NJ;

    for (;;) {
        __syncthreads();   // prior tile's smem reads complete before reuse
        if (tid == 0) *s_t = atomicAdd(&d_wq[MODE], 1);
        __syncthreads();
        const int t = *s_t;
        if (t >= NT) break;

        const int pair = d_tl[t / NJ];
        const int e    = pair >> 16;
        const int m0   = (pair & 0xFFFF) * 128;
        const int j0   = (t % NJ) * 256;
        const int cnt  = d_fill[e];
        const int off  = d_off[e];

        if (MODE == 0 && tid < 128) {
            int gm = m0 + tid;
            stok[tid] = (gm < cnt) ? d_tok[(e << 13) | gm] : -1;
        }
        __syncthreads();

        // ---- cp.async slots: A 2 chunks, B 4 chunks per thread (16B) ----
        const __half* agp[2]; unsigned aso[2], asz[2];
#pragma unroll
        for (int tt = 0; tt < 2; tt++) {
            int idx = tid + tt * 512, row = idx >> 3, c = idx & 7;
            bool ok; size_t base;
            if (MODE == 0) { int tk = stok[row]; ok = (tk >= 0); base = ok ? (size_t)tk * KD : 0; }
            else           { int gm = m0 + row;  ok = (gm < cnt); base = ok ? (size_t)(off + gm) * KD : 0; }
            agp[tt] = Amat + base + c * 8;
            asz[tt] = ok ? 16u : 0u;
            aso[tt] = row * 128 + ((c ^ (row & 7)) * 16);
        }
        const __half* bbase = Bmat + (size_t)e * CDIM * HDIM + j0;
        int bgo[4]; unsigned bso[4];
#pragma unroll
        for (int tt = 0; tt < 4; tt++) {
            int idx = tid + tt * 512, row = idx >> 5, c = idx & 31;
            bgo[tt] = row * ND + c * 8;
            bso[tt] = row * 512 + ((c ^ (row & 7)) * 16);
        }

        auto load_tile = [&](int p, int k0) {
            unsigned Ab = sA + p * 16384, Bb = sB + p * 32768;
#pragma unroll
            for (int tt = 0; tt < 2; tt++)
                asm volatile("cp.async.cg.shared.global [%0], [%1], 16, %2;"
                             :: "r"(Ab + aso[tt]), "l"(agp[tt] + k0), "r"(asz[tt]) : "memory");
            const __half* bsrc = bbase + (size_t)k0 * ND;
#pragma unroll
            for (int tt = 0; tt < 4; tt++)
                asm volatile("cp.async.cg.shared.global [%0], [%1], 16;"
                             :: "r"(Bb + bso[tt]), "l"(bsrc + bgo[tt]) : "memory");
        };

        float acc[4][4][4];
#pragma unroll
        for (int mt = 0; mt < 4; mt++)
#pragma unroll
            for (int nt = 0; nt < 4; nt++)
#pragma unroll
                for (int i = 0; i < 4; i++) acc[mt][nt][i] = 0.0f;

        load_tile(0, 0);
        asm volatile("cp.async.commit_group;" ::: "memory");
        load_tile(1, 64);
        asm volatile("cp.async.commit_group;" ::: "memory");

        for (int i = 0; i < ITERS; i++) {
            const int p = i % 3;
            asm volatile("cp.async.wait_group 1;" ::: "memory");
            __syncthreads();
            if (i + 2 < ITERS) load_tile((i + 2) % 3, (i + 2) * 64);
            asm volatile("cp.async.commit_group;" ::: "memory");

            const unsigned Ab = sA + p * 16384, Bb = sB + p * 32768;
#pragma unroll
            for (int ks = 0; ks < 4; ks++) {
                unsigned afr[4][4];
#pragma unroll
                for (int mt = 0; mt < 4; mt++) {
                    unsigned ad = Ab + (wm + mt * 16 + rsel) * 128
                                + (((ks * 2 + kh) ^ l7) * 16);
                    ldsm4(afr[mt], ad);
                }
                unsigned bfr[4][2];
#pragma unroll
                for (int bt = 0; bt < 2; bt++) {
                    int krow = ks * 16 + rsel;
                    unsigned bd = Bb + krow * 512
                                + ((((wn >> 3) + bt * 2 + kh) ^ l7) * 16);
                    unsigned r[4];
                    ldsm4t(r, bd);
                    bfr[bt * 2][0] = r[0];     bfr[bt * 2][1] = r[1];
                    bfr[bt * 2 + 1][0] = r[2]; bfr[bt * 2 + 1][1] = r[3];
                }
#pragma unroll
                for (int mt = 0; mt < 4; mt++)
#pragma unroll
                    for (int nt = 0; nt < 4; nt++)
                        mma_f16(acc[mt][nt], afr[mt], bfr[nt]);
            }
        }

        // ---- epilogue ----
#pragma unroll
        for (int mt = 0; mt < 4; mt++) {
#pragma unroll
            for (int half = 0; half < 2; half++) {
                int lrow = wm + mt * 16 + (lane >> 2) + half * 8;
                int gm   = m0 + lrow;
                if (gm >= cnt) continue;
                __half* hrow = (MODE == 0)
                    ? (d_hbufh + (size_t)(off + gm) * HDIM)
                    : (d_ybuf  + (size_t)(off + gm) * CDIM);
#pragma unroll
                for (int nt = 0; nt < 4; nt++) {
                    int col = j0 + wn + nt * 8 + (lane & 3) * 2;
                    float v0 = acc[mt][nt][half * 2 + 0] + bias[(size_t)e * ND + col];
                    float v1 = acc[mt][nt][half * 2 + 1] + bias[(size_t)e * ND + col + 1];
                    if (MODE == 0) {
                        v0 = 0.5f * v0 * (1.0f + erff(v0 * 0.70710678118654752f));
                        v1 = 0.5f * v1 * (1.0f + erff(v1 * 0.70710678118654752f));
                    }
                    *reinterpret_cast<__half2*>(hrow + col) = __floats2half2_rn(v0, v1);
                }
            }
        }
    }
}

// ---------------------------------------------------------------------------
// combine: out[tok] = w1*ybuf[row1] + w2*ybuf[row2]
// ---------------------------------------------------------------------------
__global__ void combine_kernel(float* __restrict__ out, int N) {
    int gid  = blockIdx.x * blockDim.x + threadIdx.x;
    int col4 = gid * 4;
    int tok  = col4 / CDIM;
    int c    = col4 % CDIM;
    if (tok >= N) return;

    int p1 = d_slot[tok], p2 = d_slot[MAXN + tok];
    int r1 = d_off[p1 >> 13] + (p1 & (MAXN - 1));
    int r2 = d_off[p2 >> 13] + (p2 & (MAXN - 1));
    float w1 = d_wgt[p1], w2 = d_wgt[p2];

    const __half2* a = reinterpret_cast<const __half2*>(d_ybuf + (size_t)r1 * CDIM + c);
    const __half2* b = reinterpret_cast<const __half2*>(d_ybuf + (size_t)r2 * CDIM + c);
    float2 a0 = __half22float2(a[0]), a1 = __half22float2(a[1]);
    float2 b0 = __half22float2(b[0]), b1 = __half22float2(b[1]);
    float4 o;
    o.x = w1 * a0.x + w2 * b0.x;
    o.y = w1 * a0.y + w2 * b0.y;
    o.z = w1 * a1.x + w2 * b1.x;
    o.w = w1 * a1.y + w2 * b1.y;
    *reinterpret_cast<float4*>(out + (size_t)tok * CDIM + c) = o;
}

// ---------------------------------------------------------------------------
__global__ void util_kernel(float* __restrict__ out, int NC) {
    int e = threadIdx.x;
    if (e < EXP) {
        float tot = 0.0f;
        for (int j = 0; j < EXP; j++) tot += (float)d_fill[j];
        out[NC + e] = (float)d_fill[e] / (tot + 1e-9f);
    }
}

// ---------------------------------------------------------------------------
extern "C" void kernel_launch(void* const* d_in, const int* in_sizes, int n_in,
                              void* d_out, int out_size) {
    const float* x  = (const float*)d_in[0];
    const float* Wr = (const float*)d_in[1];
    const float* W1 = (const float*)d_in[2];
    const float* b1 = (const float*)d_in[3];
    const float* W2 = (const float*)d_in[4];
    const float* b2 = (const float*)d_in[5];
    float* out = (float*)d_out;

    int N  = in_sizes[0] / CDIM;   // 8192
    int NC = N * CDIM;

    static cudaStream_t s1 = nullptr, s2 = nullptr;
    static cudaEvent_t evRoot, evW1, evX, evW2;
    static int init_done = 0;
    if (!init_done) {
        cudaFuncSetAttribute(moe_gemm<CDIM, HDIM, 0>,
                             cudaFuncAttributeMaxDynamicSharedMemorySize, GSMEM);
        cudaFuncSetAttribute(moe_gemm<HDIM, CDIM, 1>,
                             cudaFuncAttributeMaxDynamicSharedMemorySize, GSMEM);
        cudaStreamCreateWithFlags(&s1, cudaStreamNonBlocking);
        cudaStreamCreateWithFlags(&s2, cudaStreamNonBlocking);
        cudaEventCreateWithFlags(&evRoot, cudaEventDisableTiming);
        cudaEventCreateWithFlags(&evW1, cudaEventDisableTiming);
        cudaEventCreateWithFlags(&evX, cudaEventDisableTiming);
        cudaEventCreateWithFlags(&evW2, cudaEventDisableTiming);
        init_done = 1;
    }

    __half *xh, *w1h, *w2h;
    cudaGetSymbolAddress((void**)&xh,  d_xh);
    cudaGetSymbolAddress((void**)&w1h, d_w1h);
    cudaGetSymbolAddress((void**)&w2h, d_w2h);

    // ---- fork: converts on s1/s2, routing on main ----
    cudaEventRecord(evRoot, 0);
    cudaStreamWaitEvent(s1, evRoot, 0);
    cudaStreamWaitEvent(s2, evRoot, 0);

    reset_kernel<<<1, 32>>>();
    router_kernel<<<(N + 7) / 8, 256>>>(x, Wr, N);
    offsets_kernel<<<1, 32>>>();

    {
        long nw = (long)EXP * CDIM * HDIM / 8;
        cvt_half_kernel<<<(int)((nw + 255) / 256), 256, 0, s1>>>(W1, w1h, nw);
        cvt_half_kernel<<<(NC / 8 + 255) / 256, 256, 0, s2>>>(x, xh, NC / 8);
        cudaEventRecord(evX, s2);
        cvt_half_kernel<<<(int)((nw + 255) / 256), 256, 0, s2>>>(W2, w2h, nw);
    }
    cudaEventRecord(evW1, s1);
    cudaEventRecord(evW2, s2);

    // ---- gemm1: needs routing, xh, w1h ----
    cudaStreamWaitEvent(0, evW1, 0);
    cudaStreamWaitEvent(0, evX, 0);
    moe_gemm<CDIM, HDIM, 0><<<NSM, 512, GSMEM>>>(xh, w1h, b1);

    // ---- gemm2: needs w2h ----
    cudaStreamWaitEvent(0, evW2, 0);
    __half* hb; cudaGetSymbolAddress((void**)&hb, d_hbufh);
    moe_gemm<HDIM, CDIM, 1><<<NSM, 512, GSMEM>>>(hb, w2h, b2);

    combine_kernel<<<(NC / 4 + 255) / 256, 256>>>(out, N);
    util_kernel<<<1, 32>>>(out, NC);
}